// round 3
// baseline (speedup 1.0000x reference)
#include <cuda_runtime.h>
#include <math.h>

#define DIMC 256
#define NHEADS 8
#define HEADD 32
#define KEYD 16
#define HQKV 512
#define NB 16
#define NPIX 1024
#define EPSV 1e-5f
#define ATTN_SCALE 0.25f   // KEY_DIM^-0.5 = 16^-0.5

typedef unsigned long long u64;

// ---- packed fp32x2 helpers (Blackwell paired-FP32 pipe) ----
__device__ __forceinline__ u64 ffma2(u64 a, u64 b, u64 c) {
    u64 d;
    asm("fma.rn.f32x2 %0, %1, %2, %3;" : "=l"(d) : "l"(a), "l"(b), "l"(c));
    return d;
}
__device__ __forceinline__ u64 fmul2(u64 a, u64 b) {
    u64 d;
    asm("mul.rn.f32x2 %0, %1, %2;" : "=l"(d) : "l"(a), "l"(b));
    return d;
}
__device__ __forceinline__ u64 pk2(float lo, float hi) {
    u64 r;
    asm("mov.b64 %0, {%1, %2};" : "=l"(r) : "f"(lo), "f"(hi));
    return r;
}
__device__ __forceinline__ void upk2(u64 v, float& a, float& b) {
    asm("mov.b64 {%0, %1}, %2;" : "=f"(a), "=f"(b) : "l"(v));
}

// Scratch (allocation-free rule: __device__ globals)
__device__ float g_qkv_buf[(size_t)NB * HQKV * NPIX];   // 33.5 MB: qkv[b][o][p]
__device__ float g_att_buf[(size_t)NB * DIMC * NPIX];   // 16.8 MB: attended(+pos)[b][c][p]

// ---------------------------------------------------------------------------
// fp32 GEMM + BatchNorm epilogue, FFMA2 microkernel:
//   out[b][o][p] = BN( sum_c A[o][c] * In[b][c][p] )
// Tiles: BM=64 (o), BN=64 (p), BK=16. 256 threads, 4x4 microtile (packed 4x2).
// ---------------------------------------------------------------------------
__global__ void gemm_bn_kernel(const float* __restrict__ A,
                               const float* __restrict__ In,
                               float* __restrict__ Out,
                               int M,
                               const float* __restrict__ gam,
                               const float* __restrict__ bet,
                               const float* __restrict__ mu,
                               const float* __restrict__ var) {
    __shared__ float As[16][68];   // [k][o], padded (row = 272B, 16B-aligned)
    __shared__ float Bs[16][64];   // [k][p]

    const int b = blockIdx.z;
    const int oBase = blockIdx.y * 64;
    const int pBase = blockIdx.x * 64;
    const int tid = threadIdx.x;          // 0..255
    const int tx = tid & 15;              // p microtile
    const int ty = tid >> 4;              // o microtile

    const float* inb = In + (size_t)b * DIMC * NPIX;

    u64 acc[4][2];
#pragma unroll
    for (int i = 0; i < 4; i++) { acc[i][0] = 0ULL; acc[i][1] = 0ULL; }

    for (int k0 = 0; k0 < DIMC; k0 += 16) {
        // Load A tile [64 x 16] -> As[k][o] (transpose)
        {
            int row = tid >> 2;            // 0..63 (o)
            int col4 = (tid & 3) * 4;      // 0,4,8,12 (k)
            float4 wv = *(const float4*)&A[(size_t)(oBase + row) * DIMC + k0 + col4];
            As[col4 + 0][row] = wv.x;
            As[col4 + 1][row] = wv.y;
            As[col4 + 2][row] = wv.z;
            As[col4 + 3][row] = wv.w;
        }
        // Load In tile [16 x 64] -> Bs[k][p]
        {
            int row = tid >> 4;            // 0..15 (k)
            int col4 = (tid & 15) * 4;     // p
            *(float4*)&Bs[row][col4] =
                *(const float4*)&inb[(size_t)(k0 + row) * NPIX + pBase + col4];
        }
        __syncthreads();
#pragma unroll
        for (int k = 0; k < 16; k++) {
            float4 av = *(const float4*)&As[k][ty * 4];          // LDS.128
            ulonglong2 bv = *(const ulonglong2*)&Bs[k][tx * 4];  // LDS.128 (2 packed pairs)
            u64 a0 = pk2(av.x, av.x);
            u64 a1 = pk2(av.y, av.y);
            u64 a2 = pk2(av.z, av.z);
            u64 a3 = pk2(av.w, av.w);
            acc[0][0] = ffma2(a0, bv.x, acc[0][0]);
            acc[0][1] = ffma2(a0, bv.y, acc[0][1]);
            acc[1][0] = ffma2(a1, bv.x, acc[1][0]);
            acc[1][1] = ffma2(a1, bv.y, acc[1][1]);
            acc[2][0] = ffma2(a2, bv.x, acc[2][0]);
            acc[2][1] = ffma2(a2, bv.y, acc[2][1]);
            acc[3][0] = ffma2(a3, bv.x, acc[3][0]);
            acc[3][1] = ffma2(a3, bv.y, acc[3][1]);
        }
        __syncthreads();
    }

    // Epilogue: BN affine, vectorized store
#pragma unroll
    for (int i = 0; i < 4; i++) {
        int o = oBase + ty * 4 + i;
        float inv = rsqrtf(var[o] + EPSV) * gam[o];
        float add = bet[o] - mu[o] * inv;
        float4 r;
        upk2(acc[i][0], r.x, r.y);
        upk2(acc[i][1], r.z, r.w);
        r.x = r.x * inv + add;
        r.y = r.y * inv + add;
        r.z = r.z * inv + add;
        r.w = r.w * inv + add;
        *(float4*)&Out[((size_t)b * M + o) * NPIX + pBase + tx * 4] = r;
    }
}

// ---------------------------------------------------------------------------
// Flash-style attention with packed fp32x2 math, packed along the KEY dim.
// Grid = 512 CTAs: blockIdx.x -> (b,h, query-quarter). Each CTA loads the
// head's K (16x1024) + V (32x1024) into smem (192 KB) and processes 256
// queries, 1 query/thread. Accumulators hold (even-key, odd-key) partial
// sums, folded at the end. All smem reads are warp-broadcast (conflict-free).
// ---------------------------------------------------------------------------
__global__ void attn_kernel(const float* __restrict__ qkv,
                            float* __restrict__ att) {
    extern __shared__ float sm[];
    float* k_s = sm;                 // [16][1024]
    float* v_s = sm + 16 * NPIX;     // [32][1024]

    const int blk = blockIdx.x;      // 0..511
    const int bh = blk >> 2;         // 0..127
    const int qq = blk & 3;          // query quarter
    const int b = bh >> 3;
    const int h = bh & 7;
    const float* base = qkv + ((size_t)b * HQKV + h * 64) * NPIX;
    const int tid = threadIdx.x;     // 0..255

    // Load k (rows 16..31) and v (rows 32..63): 48 contiguous rows
    {
        const float4* src = (const float4*)(base + 16 * NPIX);
        float4* dst = (float4*)sm;
        for (int i = tid; i < 48 * NPIX / 4; i += 256) dst[i] = src[i];
    }
    __syncthreads();

    float* ob = att + ((size_t)b * DIMC + h * HEADD) * NPIX;
    const int q0 = qq * 256 + tid;

    float qs[16];
#pragma unroll
    for (int c = 0; c < 16; c++) qs[c] = base[c * NPIX + q0] * ATTN_SCALE;

    float m = -1e30f, l = 0.f;
    u64 o2[32];
#pragma unroll
    for (int d = 0; d < 32; d++) o2[d] = 0ULL;

    for (int kc = 0; kc < NPIX; kc += 16) {
        // ---- scores: s2[j2] = packed (s[2j2], s[2j2+1]) over 16 keys ----
        u64 s2[8];
#pragma unroll
        for (int j = 0; j < 8; j++) s2[j] = 0ULL;
#pragma unroll
        for (int c = 0; c < 16; c++) {
            u64 qd = pk2(qs[c], qs[c]);
            const ulonglong2* kp = (const ulonglong2*)(k_s + c * NPIX + kc);
            ulonglong2 k0v = kp[0], k1v = kp[1], k2v = kp[2], k3v = kp[3];
            s2[0] = ffma2(qd, k0v.x, s2[0]);
            s2[1] = ffma2(qd, k0v.y, s2[1]);
            s2[2] = ffma2(qd, k1v.x, s2[2]);
            s2[3] = ffma2(qd, k1v.y, s2[3]);
            s2[4] = ffma2(qd, k2v.x, s2[4]);
            s2[5] = ffma2(qd, k2v.y, s2[5]);
            s2[6] = ffma2(qd, k3v.x, s2[6]);
            s2[7] = ffma2(qd, k3v.y, s2[7]);
        }

        // ---- online softmax (scalar) ----
        float sv[16];
#pragma unroll
        for (int j = 0; j < 8; j++) upk2(s2[j], sv[2 * j], sv[2 * j + 1]);
        float cm = sv[0];
#pragma unroll
        for (int j = 1; j < 16; j++) cm = fmaxf(cm, sv[j]);
        float nm = fmaxf(m, cm);
        float al = __expf(m - nm);
        m = nm;
        l *= al;
        u64 al2 = pk2(al, al);
#pragma unroll
        for (int d = 0; d < 32; d++) o2[d] = fmul2(o2[d], al2);

        float pv[16];
#pragma unroll
        for (int j = 0; j < 16; j++) {
            pv[j] = __expf(sv[j] - m);
            l += pv[j];
        }
        u64 p2[8];
#pragma unroll
        for (int j = 0; j < 8; j++) p2[j] = pk2(pv[2 * j], pv[2 * j + 1]);

        // ---- output accumulation: o2[d] += p2[j2] * v2[d][j2] ----
#pragma unroll
        for (int d = 0; d < 32; d++) {
            const ulonglong2* vp = (const ulonglong2*)(v_s + d * NPIX + kc);
            ulonglong2 v0 = vp[0], v1 = vp[1], v2 = vp[2], v3 = vp[3];
            u64 a = o2[d];
            a = ffma2(p2[0], v0.x, a);
            a = ffma2(p2[1], v0.y, a);
            a = ffma2(p2[2], v1.x, a);
            a = ffma2(p2[3], v1.y, a);
            a = ffma2(p2[4], v2.x, a);
            a = ffma2(p2[5], v2.y, a);
            a = ffma2(p2[6], v3.x, a);
            a = ffma2(p2[7], v3.y, a);
            o2[d] = a;
        }
    }

    float rinv = 1.f / l;
#pragma unroll
    for (int d = 0; d < 32; d++) {
        float e, o;
        upk2(o2[d], e, o);
        ob[d * NPIX + q0] = (e + o) * rinv;
    }
}

// ---------------------------------------------------------------------------
// Depthwise 3x3 conv on v_img + BN, added into attended buffer in-place.
// v_img channel ch maps to qkv channel (ch/32)*64 + 32 + (ch%32).
// ---------------------------------------------------------------------------
__global__ void pos_conv_kernel(const float* __restrict__ qkv,
                                float* __restrict__ att,
                                const float* __restrict__ wpos,
                                const float* __restrict__ gam,
                                const float* __restrict__ bet,
                                const float* __restrict__ mu,
                                const float* __restrict__ var) {
    int idx = blockIdx.x * blockDim.x + threadIdx.x;
    if (idx >= NB * DIMC * NPIX) return;
    int p = idx & 1023;
    int ch = (idx >> 10) & 255;
    int b = idx >> 18;
    int y = p >> 5, x = p & 31;
    int o = ((ch >> 5) * 64) + 32 + (ch & 31);
    const float* vrow = qkv + ((size_t)b * HQKV + o) * NPIX;
    const float* wp = wpos + ch * 9;

    float acc = 0.f;
#pragma unroll
    for (int dy = 0; dy < 3; dy++) {
        int yy = y + dy - 1;
        if (yy < 0 || yy > 31) continue;
#pragma unroll
        for (int dx = 0; dx < 3; dx++) {
            int xx = x + dx - 1;
            if (xx < 0 || xx > 31) continue;
            acc += vrow[yy * 32 + xx] * wp[dy * 3 + dx];
        }
    }
    float inv = rsqrtf(var[ch] + EPSV) * gam[ch];
    att[idx] += acc * inv + (bet[ch] - mu[ch] * inv);
}

// ---------------------------------------------------------------------------
extern "C" void kernel_launch(void* const* d_in, const int* in_sizes, int n_in,
                              void* d_out, int out_size) {
    const float* x      = (const float*)d_in[0];
    const float* w_qkv  = (const float*)d_in[1];
    const float* g_qkv  = (const float*)d_in[2];
    const float* b_qkv  = (const float*)d_in[3];
    const float* m_qkv  = (const float*)d_in[4];
    const float* v_qkv  = (const float*)d_in[5];
    const float* w_pos  = (const float*)d_in[6];
    const float* g_pos  = (const float*)d_in[7];
    const float* b_pos  = (const float*)d_in[8];
    const float* m_pos  = (const float*)d_in[9];
    const float* v_pos  = (const float*)d_in[10];
    const float* w_proj = (const float*)d_in[11];
    const float* g_proj = (const float*)d_in[12];
    const float* b_proj = (const float*)d_in[13];
    const float* m_proj = (const float*)d_in[14];
    const float* v_proj = (const float*)d_in[15];
    float* out = (float*)d_out;

    float* qkv_buf = nullptr;
    float* att_buf = nullptr;
    cudaGetSymbolAddress((void**)&qkv_buf, g_qkv_buf);
    cudaGetSymbolAddress((void**)&att_buf, g_att_buf);

    const int attn_smem = 48 * NPIX * sizeof(float);   // 192 KB
    cudaFuncSetAttribute(attn_kernel,
                         cudaFuncAttributeMaxDynamicSharedMemorySize, attn_smem);

    // 1) QKV GEMM + BN
    gemm_bn_kernel<<<dim3(NPIX / 64, HQKV / 64, NB), 256>>>(
        w_qkv, x, qkv_buf, HQKV, g_qkv, b_qkv, m_qkv, v_qkv);

    // 2) Attention -> att_buf  (512 CTAs: 4 query-quarters per (b,h))
    attn_kernel<<<512, 256, attn_smem>>>(qkv_buf, att_buf);

    // 3) Depthwise conv + BN, add into att_buf
    pos_conv_kernel<<<(NB * DIMC * NPIX) / 256, 256>>>(
        qkv_buf, att_buf, w_pos, g_pos, b_pos, m_pos, v_pos);

    // 4) Proj GEMM + BN -> d_out
    gemm_bn_kernel<<<dim3(NPIX / 64, DIMC / 64, NB), 256>>>(
        w_proj, att_buf, out, DIMC, g_proj, b_proj, m_proj, v_proj);
}

// round 5
// speedup vs baseline: 1.5360x; 1.5360x over previous
#include <cuda_runtime.h>
#include <cuda_bf16.h>
#include <math.h>

#define DIMC 256
#define NHEADS 8
#define HEADD 32
#define KEYD 16
#define HQKV 512
#define NB 16
#define NPIX 1024
#define EPSV 1e-5f
#define ATTN_SCALE 0.25f   // KEY_DIM^-0.5 = 16^-0.5

// Scratch (allocation-free rule: __device__ globals)
__device__ float g_qkv_buf[(size_t)NB * HQKV * NPIX];   // 33.5 MB: qkv[b][o][p]
__device__ float g_att_buf[(size_t)NB * DIMC * NPIX];   // 16.8 MB: attended(+pos)[b][c][p]

// ---------------------------------------------------------------------------
// m16n8k16 bf16 MMA, fp32 accumulate (row.col)
// ---------------------------------------------------------------------------
#define MMA16816(c, a, b0v, b1v)                                              \
    asm volatile(                                                             \
        "mma.sync.aligned.m16n8k16.row.col.f32.bf16.bf16.f32 "                \
        "{%0,%1,%2,%3}, {%4,%5,%6,%7}, {%8,%9}, {%0,%1,%2,%3};"               \
        : "+f"((c)[0]), "+f"((c)[1]), "+f"((c)[2]), "+f"((c)[3])              \
        : "r"((a)[0]), "r"((a)[1]), "r"((a)[2]), "r"((a)[3]),                 \
          "r"(b0v), "r"(b1v))

// Split-pack: hi = bf16(v), lo = bf16(v - hi); element0 in low 16 bits.
__device__ __forceinline__ unsigned pack_hi2(float v0, float v1, unsigned& lo_out) {
    __nv_bfloat162 hh, ll;
    hh.x = __float2bfloat16_rn(v0);
    hh.y = __float2bfloat16_rn(v1);
    ll.x = __float2bfloat16_rn(v0 - __bfloat162float(hh.x));
    ll.y = __float2bfloat16_rn(v1 - __bfloat162float(hh.y));
    lo_out = *(unsigned*)&ll;
    return *(unsigned*)&hh;
}

// ---------------------------------------------------------------------------
// fp32 GEMM + BatchNorm epilogue (R1-proven version):
//   out[b][o][p] = BN( sum_c A[o][c] * In[b][c][p] )
// ---------------------------------------------------------------------------
__global__ void gemm_bn_kernel(const float* __restrict__ A,
                               const float* __restrict__ In,
                               float* __restrict__ Out,
                               int M,
                               const float* __restrict__ gam,
                               const float* __restrict__ bet,
                               const float* __restrict__ mu,
                               const float* __restrict__ var) {
    __shared__ float As[16][68];   // [k][o], padded
    __shared__ float Bs[16][64];   // [k][p]

    const int b = blockIdx.z;
    const int oBase = blockIdx.y * 64;
    const int pBase = blockIdx.x * 64;
    const int tid = threadIdx.x;          // 0..255
    const int tx = tid & 15;              // p microtile
    const int ty = tid >> 4;              // o microtile

    const float* inb = In + (size_t)b * DIMC * NPIX;

    float acc[4][4];
#pragma unroll
    for (int i = 0; i < 4; i++)
#pragma unroll
        for (int j = 0; j < 4; j++) acc[i][j] = 0.f;

    for (int k0 = 0; k0 < DIMC; k0 += 16) {
        {
            int row = tid >> 2;            // 0..63 (o)
            int col4 = (tid & 3) * 4;      // 0,4,8,12 (k)
            float4 wv = *(const float4*)&A[(size_t)(oBase + row) * DIMC + k0 + col4];
            As[col4 + 0][row] = wv.x;
            As[col4 + 1][row] = wv.y;
            As[col4 + 2][row] = wv.z;
            As[col4 + 3][row] = wv.w;
        }
        {
            int row = tid >> 4;            // 0..15 (k)
            int col4 = (tid & 15) * 4;     // p
            *(float4*)&Bs[row][col4] =
                *(const float4*)&inb[(size_t)(k0 + row) * NPIX + pBase + col4];
        }
        __syncthreads();
#pragma unroll
        for (int k = 0; k < 16; k++) {
            float a[4];
#pragma unroll
            for (int i = 0; i < 4; i++) a[i] = As[k][ty * 4 + i];
            float4 bv = *(const float4*)&Bs[k][tx * 4];
            float bb[4] = {bv.x, bv.y, bv.z, bv.w};
#pragma unroll
            for (int i = 0; i < 4; i++)
#pragma unroll
                for (int j = 0; j < 4; j++) acc[i][j] += a[i] * bb[j];
        }
        __syncthreads();
    }

#pragma unroll
    for (int i = 0; i < 4; i++) {
        int o = oBase + ty * 4 + i;
        float inv = rsqrtf(var[o] + EPSV) * gam[o];
        float add = bet[o] - mu[o] * inv;
        float4 r;
        r.x = acc[i][0] * inv + add;
        r.y = acc[i][1] * inv + add;
        r.z = acc[i][2] * inv + add;
        r.w = acc[i][3] * inv + add;
        *(float4*)&Out[((size_t)b * M + o) * NPIX + pBase + tx * 4] = r;
    }
}

// ---------------------------------------------------------------------------
// FlashAttention-2 with mma.sync bf16 + hi/lo split (fp32-grade precision).
// Grid = 512 CTAs: (b,h) x query-quarter. 256 threads = 8 warps.
// Warp w owns queries [qBase + 32w, qBase + 32w + 32) = 2 qtiles of 16.
// Key chunks of 64: K(16x64), V(32x64) split to bf16 hi/lo in smem.
//   Ks[key][dim]  stride 24 bf16 (48B)  -> conflict-free u32 B-frag loads
//   Vt[d][key]    stride 72 bf16 (144B) -> conflict-free u32 B-frag loads
// ---------------------------------------------------------------------------
__global__ void __launch_bounds__(256, 1)
attn_kernel(const float* __restrict__ qkv, float* __restrict__ att) {
    __shared__ __align__(16) __nv_bfloat16 Ks_h[64][24];
    __shared__ __align__(16) __nv_bfloat16 Ks_l[64][24];
    __shared__ __align__(16) __nv_bfloat16 Vt_h[32][72];
    __shared__ __align__(16) __nv_bfloat16 Vt_l[32][72];
    __shared__ float Qs[16][256];

    const int blk = blockIdx.x;      // 0..511
    const int bh = blk >> 2;
    const int qq = blk & 3;
    const int b = bh >> 3;
    const int h = bh & 7;
    const float* base = qkv + ((size_t)b * HQKV + h * 64) * NPIX;
    float* ob = att + ((size_t)b * DIMC + h * HEADD) * NPIX;

    const int tid = threadIdx.x;
    const int warp = tid >> 5;
    const int lane = tid & 31;
    const int gr = lane >> 2;        // fragment group row / group col
    const int tc = lane & 3;
    const int qBase = qq * 256;

    // ---- stage Q (scaled) and build per-warp Q fragments (hi/lo) ----
    for (int idx = tid; idx < 16 * 256; idx += 256) {
        int c = idx >> 8, p = idx & 255;
        Qs[c][p] = base[c * NPIX + qBase + p] * ATTN_SCALE;
    }
    __syncthreads();

    unsigned qf[2][2][4];            // [qtile][hi/lo][reg]
#pragma unroll
    for (int qt = 0; qt < 2; qt++) {
        int q0 = warp * 32 + qt * 16 + gr;
#pragma unroll
        for (int r = 0; r < 4; r++) {
            int row = q0 + ((r & 1) ? 8 : 0);
            int k0 = 2 * tc + ((r & 2) ? 8 : 0);
            qf[qt][0][r] = pack_hi2(Qs[k0][row], Qs[k0 + 1][row], qf[qt][1][r]);
        }
    }

    float m[2][2], l[2][2];
    float O[2][4][4];
#pragma unroll
    for (int qt = 0; qt < 2; qt++) {
        m[qt][0] = -1e30f; m[qt][1] = -1e30f;
        l[qt][0] = 0.f;    l[qt][1] = 0.f;
#pragma unroll
        for (int dt = 0; dt < 4; dt++)
#pragma unroll
            for (int r = 0; r < 4; r++) O[qt][dt][r] = 0.f;
    }

    for (int kb = 0; kb < NPIX; kb += 64) {
        __syncthreads();   // previous chunk compute done before overwrite
        // ---- load + split K chunk (16 dims x 64 keys), transposed ----
#pragma unroll
        for (int j = 0; j < 4; j++) {
            int idx = tid + j * 256;
            int c = idx >> 6, i = idx & 63;
            float v = base[(16 + c) * NPIX + kb + i];
            __nv_bfloat16 hi = __float2bfloat16_rn(v);
            Ks_h[i][c] = hi;
            Ks_l[i][c] = __float2bfloat16_rn(v - __bfloat162float(hi));
        }
        // ---- load + split V chunk (32 dims x 64 keys) ----
#pragma unroll
        for (int j = 0; j < 8; j++) {
            int idx = tid + j * 256;
            int d = idx >> 6, i = idx & 63;
            float v = base[(32 + d) * NPIX + kb + i];
            __nv_bfloat16 hi = __float2bfloat16_rn(v);
            Vt_h[d][i] = hi;
            Vt_l[d][i] = __float2bfloat16_rn(v - __bfloat162float(hi));
        }
        __syncthreads();

#pragma unroll
        for (int qt = 0; qt < 2; qt++) {
            // ---- scores S[qt]: 8 ntiles of 8 keys, 3-MMA split each ----
            float S[8][4];
#pragma unroll
            for (int nt = 0; nt < 8; nt++) {
                S[nt][0] = 0.f; S[nt][1] = 0.f; S[nt][2] = 0.f; S[nt][3] = 0.f;
                const int kr = nt * 8 + gr;
                unsigned bh0 = *(const unsigned*)&Ks_h[kr][2 * tc];
                unsigned bh1 = *(const unsigned*)&Ks_h[kr][2 * tc + 8];
                unsigned bl0 = *(const unsigned*)&Ks_l[kr][2 * tc];
                unsigned bl1 = *(const unsigned*)&Ks_l[kr][2 * tc + 8];
                MMA16816(S[nt], qf[qt][0], bh0, bh1);   // hi*hi
                MMA16816(S[nt], qf[qt][0], bl0, bl1);   // hi*lo
                MMA16816(S[nt], qf[qt][1], bh0, bh1);   // lo*hi
            }

            // ---- online softmax (rows gr and gr+8 of this qtile) ----
            float mx0 = -1e30f, mx1 = -1e30f;
#pragma unroll
            for (int nt = 0; nt < 8; nt++) {
                mx0 = fmaxf(mx0, fmaxf(S[nt][0], S[nt][1]));
                mx1 = fmaxf(mx1, fmaxf(S[nt][2], S[nt][3]));
            }
            mx0 = fmaxf(mx0, __shfl_xor_sync(0xffffffffu, mx0, 1));
            mx0 = fmaxf(mx0, __shfl_xor_sync(0xffffffffu, mx0, 2));
            mx1 = fmaxf(mx1, __shfl_xor_sync(0xffffffffu, mx1, 1));
            mx1 = fmaxf(mx1, __shfl_xor_sync(0xffffffffu, mx1, 2));

            float nm0 = fmaxf(m[qt][0], mx0);
            float nm1 = fmaxf(m[qt][1], mx1);
            float al0 = __expf(m[qt][0] - nm0);
            float al1 = __expf(m[qt][1] - nm1);
            m[qt][0] = nm0; m[qt][1] = nm1;

            float ls0 = 0.f, ls1 = 0.f;
#pragma unroll
            for (int nt = 0; nt < 8; nt++) {
                S[nt][0] = __expf(S[nt][0] - nm0);
                S[nt][1] = __expf(S[nt][1] - nm0);
                S[nt][2] = __expf(S[nt][2] - nm1);
                S[nt][3] = __expf(S[nt][3] - nm1);
                ls0 += S[nt][0] + S[nt][1];
                ls1 += S[nt][2] + S[nt][3];
            }
            ls0 += __shfl_xor_sync(0xffffffffu, ls0, 1);
            ls0 += __shfl_xor_sync(0xffffffffu, ls0, 2);
            ls1 += __shfl_xor_sync(0xffffffffu, ls1, 1);
            ls1 += __shfl_xor_sync(0xffffffffu, ls1, 2);
            l[qt][0] = l[qt][0] * al0 + ls0;
            l[qt][1] = l[qt][1] * al1 + ls1;

            // ---- rescale O ----
#pragma unroll
            for (int dt = 0; dt < 4; dt++) {
                O[qt][dt][0] *= al0; O[qt][dt][1] *= al0;
                O[qt][dt][2] *= al1; O[qt][dt][3] *= al1;
            }

            // ---- AV: O[q,d] += P[q,k] V[k,d], 4 ksteps of 16 keys ----
#pragma unroll
            for (int ks = 0; ks < 4; ks++) {
                // P A-fragment from S accums (FA2 C->A identity), split hi/lo
                unsigned ph[4], pl[4];
                ph[0] = pack_hi2(S[2 * ks][0],     S[2 * ks][1],     pl[0]);
                ph[1] = pack_hi2(S[2 * ks][2],     S[2 * ks][3],     pl[1]);
                ph[2] = pack_hi2(S[2 * ks + 1][0], S[2 * ks + 1][1], pl[2]);
                ph[3] = pack_hi2(S[2 * ks + 1][2], S[2 * ks + 1][3], pl[3]);
#pragma unroll
                for (int dt = 0; dt < 4; dt++) {
                    const int dr = dt * 8 + gr;
                    const int kc = ks * 16 + 2 * tc;
                    unsigned vh0 = *(const unsigned*)&Vt_h[dr][kc];
                    unsigned vh1 = *(const unsigned*)&Vt_h[dr][kc + 8];
                    unsigned vl0 = *(const unsigned*)&Vt_l[dr][kc];
                    unsigned vl1 = *(const unsigned*)&Vt_l[dr][kc + 8];
                    MMA16816(O[qt][dt], ph, vh0, vh1);   // hi*hi
                    MMA16816(O[qt][dt], ph, vl0, vl1);   // hi*lo
                    MMA16816(O[qt][dt], pl, vh0, vh1);   // lo*hi
                }
            }
        }
    }

    // ---- epilogue: normalize and write out[d][q] ----
#pragma unroll
    for (int qt = 0; qt < 2; qt++) {
        float r0 = 1.f / l[qt][0];
        float r1 = 1.f / l[qt][1];
        int q0 = qBase + warp * 32 + qt * 16 + gr;
        int q1 = q0 + 8;
#pragma unroll
        for (int dt = 0; dt < 4; dt++) {
            int d = dt * 8 + 2 * tc;
            ob[(size_t)d * NPIX + q0]       = O[qt][dt][0] * r0;
            ob[(size_t)(d + 1) * NPIX + q0] = O[qt][dt][1] * r0;
            ob[(size_t)d * NPIX + q1]       = O[qt][dt][2] * r1;
            ob[(size_t)(d + 1) * NPIX + q1] = O[qt][dt][3] * r1;
        }
    }
}

// ---------------------------------------------------------------------------
// Depthwise 3x3 conv on v_img + BN, added into attended buffer in-place.
// ---------------------------------------------------------------------------
__global__ void pos_conv_kernel(const float* __restrict__ qkv,
                                float* __restrict__ att,
                                const float* __restrict__ wpos,
                                const float* __restrict__ gam,
                                const float* __restrict__ bet,
                                const float* __restrict__ mu,
                                const float* __restrict__ var) {
    int idx = blockIdx.x * blockDim.x + threadIdx.x;
    if (idx >= NB * DIMC * NPIX) return;
    int p = idx & 1023;
    int ch = (idx >> 10) & 255;
    int b = idx >> 18;
    int y = p >> 5, x = p & 31;
    int o = ((ch >> 5) * 64) + 32 + (ch & 31);
    const float* vrow = qkv + ((size_t)b * HQKV + o) * NPIX;
    const float* wp = wpos + ch * 9;

    float acc = 0.f;
#pragma unroll
    for (int dy = 0; dy < 3; dy++) {
        int yy = y + dy - 1;
        if (yy < 0 || yy > 31) continue;
#pragma unroll
        for (int dx = 0; dx < 3; dx++) {
            int xx = x + dx - 1;
            if (xx < 0 || xx > 31) continue;
            acc += vrow[yy * 32 + xx] * wp[dy * 3 + dx];
        }
    }
    float inv = rsqrtf(var[ch] + EPSV) * gam[ch];
    att[idx] += acc * inv + (bet[ch] - mu[ch] * inv);
}

// ---------------------------------------------------------------------------
extern "C" void kernel_launch(void* const* d_in, const int* in_sizes, int n_in,
                              void* d_out, int out_size) {
    const float* x      = (const float*)d_in[0];
    const float* w_qkv  = (const float*)d_in[1];
    const float* g_qkv  = (const float*)d_in[2];
    const float* b_qkv  = (const float*)d_in[3];
    const float* m_qkv  = (const float*)d_in[4];
    const float* v_qkv  = (const float*)d_in[5];
    const float* w_pos  = (const float*)d_in[6];
    const float* g_pos  = (const float*)d_in[7];
    const float* b_pos  = (const float*)d_in[8];
    const float* m_pos  = (const float*)d_in[9];
    const float* v_pos  = (const float*)d_in[10];
    const float* w_proj = (const float*)d_in[11];
    const float* g_proj = (const float*)d_in[12];
    const float* b_proj = (const float*)d_in[13];
    const float* m_proj = (const float*)d_in[14];
    const float* v_proj = (const float*)d_in[15];
    float* out = (float*)d_out;

    float* qkv_buf = nullptr;
    float* att_buf = nullptr;
    cudaGetSymbolAddress((void**)&qkv_buf, g_qkv_buf);
    cudaGetSymbolAddress((void**)&att_buf, g_att_buf);

    // 1) QKV GEMM + BN
    gemm_bn_kernel<<<dim3(NPIX / 64, HQKV / 64, NB), 256>>>(
        w_qkv, x, qkv_buf, HQKV, g_qkv, b_qkv, m_qkv, v_qkv);

    // 2) Attention -> att_buf (tensor-core FA2, bf16x3 split)
    attn_kernel<<<512, 256>>>(qkv_buf, att_buf);

    // 3) Depthwise conv + BN, add into att_buf
    pos_conv_kernel<<<(NB * DIMC * NPIX) / 256, 256>>>(
        qkv_buf, att_buf, w_pos, g_pos, b_pos, m_pos, v_pos);

    // 4) Proj GEMM + BN -> d_out
    gemm_bn_kernel<<<dim3(NPIX / 64, DIMC / 64, NB), 256>>>(
        w_proj, att_buf, out, DIMC, g_proj, b_proj, m_proj, v_proj);
}

// round 6
// speedup vs baseline: 1.7714x; 1.1533x over previous
#include <cuda_runtime.h>
#include <cuda_bf16.h>
#include <math.h>

#define DIMC 256
#define NHEADS 8
#define HEADD 32
#define KEYD 16
#define HQKV 512
#define NB 16
#define NPIX 1024
#define EPSV 1e-5f
#define ATTN_SCALE 0.25f   // KEY_DIM^-0.5 = 16^-0.5

// Scratch (allocation-free rule: __device__ globals)
__device__ float g_qkv_buf[(size_t)NB * HQKV * NPIX];   // 33.5 MB: qkv[b][o][p]
__device__ float g_att_buf[(size_t)NB * DIMC * NPIX];   // 16.8 MB
// K/V pre-split bf16 planes per (b,h): rows 0-15 k_hi, 16-31 k_lo, 32-63 v_hi, 64-95 v_lo
__device__ __nv_bfloat16 g_kv_bf[(size_t)NB * NHEADS * 96 * NPIX];  // 25 MB

// ---------------------------------------------------------------------------
// m16n8k16 bf16 MMA, fp32 accumulate (row.col)
// ---------------------------------------------------------------------------
#define MMA16816(c, a, b0v, b1v)                                              \
    asm volatile(                                                             \
        "mma.sync.aligned.m16n8k16.row.col.f32.bf16.bf16.f32 "                \
        "{%0,%1,%2,%3}, {%4,%5,%6,%7}, {%8,%9}, {%0,%1,%2,%3};"               \
        : "+f"((c)[0]), "+f"((c)[1]), "+f"((c)[2]), "+f"((c)[3])              \
        : "r"((a)[0]), "r"((a)[1]), "r"((a)[2]), "r"((a)[3]),                 \
          "r"(b0v), "r"(b1v))

// Split-pack: hi = bf16(v), lo = bf16(v - hi); element0 in low 16 bits.
__device__ __forceinline__ unsigned pack_hi2(float v0, float v1, unsigned& lo_out) {
    __nv_bfloat162 hh, ll;
    hh.x = __float2bfloat16_rn(v0);
    hh.y = __float2bfloat16_rn(v1);
    ll.x = __float2bfloat16_rn(v0 - __bfloat162float(hh.x));
    ll.y = __float2bfloat16_rn(v1 - __bfloat162float(hh.y));
    lo_out = *(unsigned*)&ll;
    return *(unsigned*)&hh;
}

// Single-instruction pack of 2 floats -> bf16x2 (lo in bits [15:0]).
__device__ __forceinline__ unsigned pack_bf16x2(float lo, float hi) {
    unsigned r;
    asm("cvt.rn.bf16x2.f32 %0, %1, %2;" : "=r"(r) : "f"(hi), "f"(lo));
    return r;
}

// ---------------------------------------------------------------------------
// fp32 GEMM + BatchNorm epilogue. If kvbuf != nullptr (qkv GEMM), also emits
// bf16 hi/lo planes for the k and v channels into g_kv_bf layout.
// ---------------------------------------------------------------------------
__global__ void gemm_bn_kernel(const float* __restrict__ A,
                               const float* __restrict__ In,
                               float* __restrict__ Out,
                               int M,
                               const float* __restrict__ gam,
                               const float* __restrict__ bet,
                               const float* __restrict__ mu,
                               const float* __restrict__ var,
                               __nv_bfloat16* __restrict__ kvbuf) {
    __shared__ float As[16][68];   // [k][o], padded
    __shared__ float Bs[16][64];   // [k][p]

    const int b = blockIdx.z;
    const int oBase = blockIdx.y * 64;
    const int pBase = blockIdx.x * 64;
    const int tid = threadIdx.x;          // 0..255
    const int tx = tid & 15;              // p microtile
    const int ty = tid >> 4;              // o microtile

    const float* inb = In + (size_t)b * DIMC * NPIX;

    float acc[4][4];
#pragma unroll
    for (int i = 0; i < 4; i++)
#pragma unroll
        for (int j = 0; j < 4; j++) acc[i][j] = 0.f;

    for (int k0 = 0; k0 < DIMC; k0 += 16) {
        {
            int row = tid >> 2;            // 0..63 (o)
            int col4 = (tid & 3) * 4;      // 0,4,8,12 (k)
            float4 wv = *(const float4*)&A[(size_t)(oBase + row) * DIMC + k0 + col4];
            As[col4 + 0][row] = wv.x;
            As[col4 + 1][row] = wv.y;
            As[col4 + 2][row] = wv.z;
            As[col4 + 3][row] = wv.w;
        }
        {
            int row = tid >> 4;            // 0..15 (k)
            int col4 = (tid & 15) * 4;     // p
            *(float4*)&Bs[row][col4] =
                *(const float4*)&inb[(size_t)(k0 + row) * NPIX + pBase + col4];
        }
        __syncthreads();
#pragma unroll
        for (int k = 0; k < 16; k++) {
            float a[4];
#pragma unroll
            for (int i = 0; i < 4; i++) a[i] = As[k][ty * 4 + i];
            float4 bv = *(const float4*)&Bs[k][tx * 4];
            float bb[4] = {bv.x, bv.y, bv.z, bv.w};
#pragma unroll
            for (int i = 0; i < 4; i++)
#pragma unroll
                for (int j = 0; j < 4; j++) acc[i][j] += a[i] * bb[j];
        }
        __syncthreads();
    }

#pragma unroll
    for (int i = 0; i < 4; i++) {
        int o = oBase + ty * 4 + i;
        float inv = rsqrtf(var[o] + EPSV) * gam[o];
        float add = bet[o] - mu[o] * inv;
        float4 r;
        r.x = acc[i][0] * inv + add;
        r.y = acc[i][1] * inv + add;
        r.z = acc[i][2] * inv + add;
        r.w = acc[i][3] * inv + add;
        *(float4*)&Out[((size_t)b * M + o) * NPIX + pBase + tx * 4] = r;

        if (kvbuf != nullptr) {
            int r64 = o & 63;
            if (r64 >= 16) {               // k or v channel
                int h = o >> 6;
                int hi_row = (r64 < 32) ? (r64 - 16) : r64;          // kh:0-15, vh:32-63
                int lo_row = hi_row + ((r64 < 32) ? 16 : 32);        // kl:16-31, vl:64-95
                float vals[4] = {r.x, r.y, r.z, r.w};
                __nv_bfloat16 hb[4], lb[4];
#pragma unroll
                for (int j = 0; j < 4; j++) {
                    hb[j] = __float2bfloat16_rn(vals[j]);
                    lb[j] = __float2bfloat16_rn(vals[j] - __bfloat162float(hb[j]));
                }
                size_t hbase = (((size_t)b * NHEADS + h) * 96) * NPIX + pBase + tx * 4;
                *(uint2*)&kvbuf[hbase + (size_t)hi_row * NPIX] = *(uint2*)hb;
                *(uint2*)&kvbuf[hbase + (size_t)lo_row * NPIX] = *(uint2*)lb;
            }
        }
    }
}

// ---------------------------------------------------------------------------
// FlashAttention-2, mma.sync bf16. K/V arrive pre-split as bf16 planes.
// Grid = 512 CTAs: (b,h) x query-quarter. 256 threads = 8 warps.
// Per 64-key chunk: staging = pure u32 copies with register prefetch.
// QK uses 3-MMA hi/lo split; AV uses 2 MMAs (P_hi x V_hi + P_hi x V_lo).
// ---------------------------------------------------------------------------
__global__ void __launch_bounds__(256, 1)
attn_kernel(const float* __restrict__ qkv,
            const __nv_bfloat16* __restrict__ kvbf,
            float* __restrict__ att) {
    __shared__ __align__(16) __nv_bfloat16 Ks_h[64][24];
    __shared__ __align__(16) __nv_bfloat16 Ks_l[64][24];
    __shared__ __align__(16) __nv_bfloat16 Vt_h[32][72];
    __shared__ __align__(16) __nv_bfloat16 Vt_l[32][72];
    __shared__ float Qs[16][256];

    const int blk = blockIdx.x;      // 0..511
    const int bh = blk >> 2;
    const int qq = blk & 3;
    const int b = bh >> 3;
    const int h = bh & 7;
    const float* base = qkv + ((size_t)b * HQKV + h * 64) * NPIX;
    const unsigned* kv32 = (const unsigned*)(kvbf + ((size_t)b * NHEADS + h) * 96 * NPIX);
    float* ob = att + ((size_t)b * DIMC + h * HEADD) * NPIX;

    const int tid = threadIdx.x;
    const int warp = tid >> 5;
    const int lane = tid & 31;
    const int gr = lane >> 2;
    const int tc = lane & 3;
    const int qBase = qq * 256;

    // per-thread staging indices (u32 granularity; each u32 = 2 keys)
    const int kc0 = tid >> 5;            // K plane row for j=0 (0..7)
    const int ki0 = tid & 31;            // u32 col within 32-u32 chunk row
    const int vd0 = tid >> 5;            // V plane row base for j slices

    unsigned kr[4], vr[8];

    // ---- stage Q (scaled) ----
    for (int idx = tid; idx < 16 * 256; idx += 256) {
        int c = idx >> 8, p = idx & 255;
        Qs[c][p] = base[c * NPIX + qBase + p] * ATTN_SCALE;
    }

    // ---- prefetch chunk 0 ----
    {
        const int kb2 = 0;
#pragma unroll
        for (int j = 0; j < 2; j++) {
            int c = kc0 + j * 8;
            kr[j]     = kv32[(size_t)c * 512 + kb2 + ki0];          // k_hi
            kr[2 + j] = kv32[(size_t)(16 + c) * 512 + kb2 + ki0];   // k_lo
        }
#pragma unroll
        for (int j = 0; j < 4; j++) {
            int d = vd0 + j * 8;
            vr[j]     = kv32[(size_t)(32 + d) * 512 + kb2 + ki0];   // v_hi
            vr[4 + j] = kv32[(size_t)(64 + d) * 512 + kb2 + ki0];   // v_lo
        }
    }
    __syncthreads();   // Qs ready (kv still in regs)

    // ---- store chunk 0 to smem ----
#pragma unroll
    for (int j = 0; j < 2; j++) {
        int c = kc0 + j * 8;
        __nv_bfloat162 vh = *(__nv_bfloat162*)&kr[j];
        Ks_h[2 * ki0][c] = vh.x;
        Ks_h[2 * ki0 + 1][c] = vh.y;
        __nv_bfloat162 vl = *(__nv_bfloat162*)&kr[2 + j];
        Ks_l[2 * ki0][c] = vl.x;
        Ks_l[2 * ki0 + 1][c] = vl.y;
    }
#pragma unroll
    for (int j = 0; j < 4; j++) {
        int d = vd0 + j * 8;
        *(unsigned*)&Vt_h[d][2 * ki0] = vr[j];
        *(unsigned*)&Vt_l[d][2 * ki0] = vr[4 + j];
    }
    __syncthreads();

    // ---- Q fragments (hi/lo) ----
    unsigned qf[2][2][4];
#pragma unroll
    for (int qt = 0; qt < 2; qt++) {
        int q0 = warp * 32 + qt * 16 + gr;
#pragma unroll
        for (int r = 0; r < 4; r++) {
            int row = q0 + ((r & 1) ? 8 : 0);
            int k0 = 2 * tc + ((r & 2) ? 8 : 0);
            qf[qt][0][r] = pack_hi2(Qs[k0][row], Qs[k0 + 1][row], qf[qt][1][r]);
        }
    }

    float m[2][2], l[2][2];
    float O[2][4][4];
#pragma unroll
    for (int qt = 0; qt < 2; qt++) {
        m[qt][0] = -1e30f; m[qt][1] = -1e30f;
        l[qt][0] = 0.f;    l[qt][1] = 0.f;
#pragma unroll
        for (int dt = 0; dt < 4; dt++)
#pragma unroll
            for (int r = 0; r < 4; r++) O[qt][dt][r] = 0.f;
    }

    for (int kb = 0; kb < NPIX; kb += 64) {
        const bool more = (kb + 64 < NPIX);
        // ---- prefetch next chunk into regs (overlaps compute) ----
        if (more) {
            const int kb2 = (kb + 64) >> 1;
#pragma unroll
            for (int j = 0; j < 2; j++) {
                int c = kc0 + j * 8;
                kr[j]     = kv32[(size_t)c * 512 + kb2 + ki0];
                kr[2 + j] = kv32[(size_t)(16 + c) * 512 + kb2 + ki0];
            }
#pragma unroll
            for (int j = 0; j < 4; j++) {
                int d = vd0 + j * 8;
                vr[j]     = kv32[(size_t)(32 + d) * 512 + kb2 + ki0];
                vr[4 + j] = kv32[(size_t)(64 + d) * 512 + kb2 + ki0];
            }
        }

#pragma unroll
        for (int qt = 0; qt < 2; qt++) {
            // ---- scores: 8 ntiles of 8 keys, 3-MMA split each ----
            float S[8][4];
#pragma unroll
            for (int nt = 0; nt < 8; nt++) {
                S[nt][0] = 0.f; S[nt][1] = 0.f; S[nt][2] = 0.f; S[nt][3] = 0.f;
                const int krow = nt * 8 + gr;
                unsigned bh0 = *(const unsigned*)&Ks_h[krow][2 * tc];
                unsigned bh1 = *(const unsigned*)&Ks_h[krow][2 * tc + 8];
                unsigned bl0 = *(const unsigned*)&Ks_l[krow][2 * tc];
                unsigned bl1 = *(const unsigned*)&Ks_l[krow][2 * tc + 8];
                MMA16816(S[nt], qf[qt][0], bh0, bh1);   // hi*hi
                MMA16816(S[nt], qf[qt][0], bl0, bl1);   // hi*lo
                MMA16816(S[nt], qf[qt][1], bh0, bh1);   // lo*hi
            }

            // ---- online softmax ----
            float mx0 = -1e30f, mx1 = -1e30f;
#pragma unroll
            for (int nt = 0; nt < 8; nt++) {
                mx0 = fmaxf(mx0, fmaxf(S[nt][0], S[nt][1]));
                mx1 = fmaxf(mx1, fmaxf(S[nt][2], S[nt][3]));
            }
            mx0 = fmaxf(mx0, __shfl_xor_sync(0xffffffffu, mx0, 1));
            mx0 = fmaxf(mx0, __shfl_xor_sync(0xffffffffu, mx0, 2));
            mx1 = fmaxf(mx1, __shfl_xor_sync(0xffffffffu, mx1, 1));
            mx1 = fmaxf(mx1, __shfl_xor_sync(0xffffffffu, mx1, 2));

            float nm0 = fmaxf(m[qt][0], mx0);
            float nm1 = fmaxf(m[qt][1], mx1);
            float al0 = __expf(m[qt][0] - nm0);
            float al1 = __expf(m[qt][1] - nm1);
            m[qt][0] = nm0; m[qt][1] = nm1;

            float ls0 = 0.f, ls1 = 0.f;
#pragma unroll
            for (int nt = 0; nt < 8; nt++) {
                S[nt][0] = __expf(S[nt][0] - nm0);
                S[nt][1] = __expf(S[nt][1] - nm0);
                S[nt][2] = __expf(S[nt][2] - nm1);
                S[nt][3] = __expf(S[nt][3] - nm1);
                ls0 += S[nt][0] + S[nt][1];
                ls1 += S[nt][2] + S[nt][3];
            }
            ls0 += __shfl_xor_sync(0xffffffffu, ls0, 1);
            ls0 += __shfl_xor_sync(0xffffffffu, ls0, 2);
            ls1 += __shfl_xor_sync(0xffffffffu, ls1, 1);
            ls1 += __shfl_xor_sync(0xffffffffu, ls1, 2);
            l[qt][0] = l[qt][0] * al0 + ls0;
            l[qt][1] = l[qt][1] * al1 + ls1;

#pragma unroll
            for (int dt = 0; dt < 4; dt++) {
                O[qt][dt][0] *= al0; O[qt][dt][1] *= al0;
                O[qt][dt][2] *= al1; O[qt][dt][3] *= al1;
            }

            // ---- AV: 2 MMAs per tile (P_hi only) ----
#pragma unroll
            for (int ks = 0; ks < 4; ks++) {
                unsigned ph[4];
                ph[0] = pack_bf16x2(S[2 * ks][0],     S[2 * ks][1]);
                ph[1] = pack_bf16x2(S[2 * ks][2],     S[2 * ks][3]);
                ph[2] = pack_bf16x2(S[2 * ks + 1][0], S[2 * ks + 1][1]);
                ph[3] = pack_bf16x2(S[2 * ks + 1][2], S[2 * ks + 1][3]);
#pragma unroll
                for (int dt = 0; dt < 4; dt++) {
                    const int dr = dt * 8 + gr;
                    const int kc = ks * 16 + 2 * tc;
                    unsigned vh0 = *(const unsigned*)&Vt_h[dr][kc];
                    unsigned vh1 = *(const unsigned*)&Vt_h[dr][kc + 8];
                    unsigned vl0 = *(const unsigned*)&Vt_l[dr][kc];
                    unsigned vl1 = *(const unsigned*)&Vt_l[dr][kc + 8];
                    MMA16816(O[qt][dt], ph, vh0, vh1);
                    MMA16816(O[qt][dt], ph, vl0, vl1);
                }
            }
        }

        // ---- commit prefetched chunk to smem ----
        if (more) {
            __syncthreads();
#pragma unroll
            for (int j = 0; j < 2; j++) {
                int c = kc0 + j * 8;
                __nv_bfloat162 vh = *(__nv_bfloat162*)&kr[j];
                Ks_h[2 * ki0][c] = vh.x;
                Ks_h[2 * ki0 + 1][c] = vh.y;
                __nv_bfloat162 vl = *(__nv_bfloat162*)&kr[2 + j];
                Ks_l[2 * ki0][c] = vl.x;
                Ks_l[2 * ki0 + 1][c] = vl.y;
            }
#pragma unroll
            for (int j = 0; j < 4; j++) {
                int d = vd0 + j * 8;
                *(unsigned*)&Vt_h[d][2 * ki0] = vr[j];
                *(unsigned*)&Vt_l[d][2 * ki0] = vr[4 + j];
            }
            __syncthreads();
        }
    }

    // ---- epilogue ----
#pragma unroll
    for (int qt = 0; qt < 2; qt++) {
        float r0 = 1.f / l[qt][0];
        float r1 = 1.f / l[qt][1];
        int q0 = qBase + warp * 32 + qt * 16 + gr;
        int q1 = q0 + 8;
#pragma unroll
        for (int dt = 0; dt < 4; dt++) {
            int d = dt * 8 + 2 * tc;
            ob[(size_t)d * NPIX + q0]       = O[qt][dt][0] * r0;
            ob[(size_t)(d + 1) * NPIX + q0] = O[qt][dt][1] * r0;
            ob[(size_t)d * NPIX + q1]       = O[qt][dt][2] * r1;
            ob[(size_t)(d + 1) * NPIX + q1] = O[qt][dt][3] * r1;
        }
    }
}

// ---------------------------------------------------------------------------
// Depthwise 3x3 conv on v_img + BN, added into attended buffer in-place.
// ---------------------------------------------------------------------------
__global__ void pos_conv_kernel(const float* __restrict__ qkv,
                                float* __restrict__ att,
                                const float* __restrict__ wpos,
                                const float* __restrict__ gam,
                                const float* __restrict__ bet,
                                const float* __restrict__ mu,
                                const float* __restrict__ var) {
    int idx = blockIdx.x * blockDim.x + threadIdx.x;
    if (idx >= NB * DIMC * NPIX) return;
    int p = idx & 1023;
    int ch = (idx >> 10) & 255;
    int b = idx >> 18;
    int y = p >> 5, x = p & 31;
    int o = ((ch >> 5) * 64) + 32 + (ch & 31);
    const float* vrow = qkv + ((size_t)b * HQKV + o) * NPIX;
    const float* wp = wpos + ch * 9;

    float acc = 0.f;
#pragma unroll
    for (int dy = 0; dy < 3; dy++) {
        int yy = y + dy - 1;
        if (yy < 0 || yy > 31) continue;
#pragma unroll
        for (int dx = 0; dx < 3; dx++) {
            int xx = x + dx - 1;
            if (xx < 0 || xx > 31) continue;
            acc += vrow[yy * 32 + xx] * wp[dy * 3 + dx];
        }
    }
    float inv = rsqrtf(var[ch] + EPSV) * gam[ch];
    att[idx] += acc * inv + (bet[ch] - mu[ch] * inv);
}

// ---------------------------------------------------------------------------
extern "C" void kernel_launch(void* const* d_in, const int* in_sizes, int n_in,
                              void* d_out, int out_size) {
    const float* x      = (const float*)d_in[0];
    const float* w_qkv  = (const float*)d_in[1];
    const float* g_qkv  = (const float*)d_in[2];
    const float* b_qkv  = (const float*)d_in[3];
    const float* m_qkv  = (const float*)d_in[4];
    const float* v_qkv  = (const float*)d_in[5];
    const float* w_pos  = (const float*)d_in[6];
    const float* g_pos  = (const float*)d_in[7];
    const float* b_pos  = (const float*)d_in[8];
    const float* m_pos  = (const float*)d_in[9];
    const float* v_pos  = (const float*)d_in[10];
    const float* w_proj = (const float*)d_in[11];
    const float* g_proj = (const float*)d_in[12];
    const float* b_proj = (const float*)d_in[13];
    const float* m_proj = (const float*)d_in[14];
    const float* v_proj = (const float*)d_in[15];
    float* out = (float*)d_out;

    float* qkv_buf = nullptr;
    float* att_buf = nullptr;
    __nv_bfloat16* kv_bf = nullptr;
    cudaGetSymbolAddress((void**)&qkv_buf, g_qkv_buf);
    cudaGetSymbolAddress((void**)&att_buf, g_att_buf);
    cudaGetSymbolAddress((void**)&kv_bf, g_kv_bf);

    // 1) QKV GEMM + BN (+ bf16 hi/lo K/V plane emission)
    gemm_bn_kernel<<<dim3(NPIX / 64, HQKV / 64, NB), 256>>>(
        w_qkv, x, qkv_buf, HQKV, g_qkv, b_qkv, m_qkv, v_qkv, kv_bf);

    // 2) Attention -> att_buf (tensor-core FA2, pre-split K/V)
    attn_kernel<<<512, 256>>>(qkv_buf, kv_bf, att_buf);

    // 3) Depthwise conv + BN, add into att_buf
    pos_conv_kernel<<<(NB * DIMC * NPIX) / 256, 256>>>(
        qkv_buf, att_buf, w_pos, g_pos, b_pos, m_pos, v_pos);

    // 4) Proj GEMM + BN -> d_out
    gemm_bn_kernel<<<dim3(NPIX / 64, DIMC / 64, NB), 256>>>(
        w_proj, att_buf, out, DIMC, g_proj, b_proj, m_proj, v_proj, nullptr);
}

// round 7
// speedup vs baseline: 2.2159x; 1.2509x over previous
#include <cuda_runtime.h>
#include <cuda_bf16.h>
#include <math.h>

#define DIMC 256
#define NHEADS 8
#define HEADD 32
#define KEYD 16
#define HQKV 512
#define NB 16
#define NPIX 1024
#define EPSV 1e-5f
#define ATTN_SCALE 0.25f   // KEY_DIM^-0.5 = 16^-0.5

// Scratch (allocation-free rule: __device__ globals)
__device__ float g_qkv_buf[(size_t)NB * HQKV * NPIX];   // 33.5 MB: qkv[b][o][p]
__device__ float g_att_buf[(size_t)NB * DIMC * NPIX];   // 16.8 MB
// K/V pre-split bf16 planes per (b,h): rows 0-15 k_hi, 16-31 k_lo, 32-63 v_hi, 64-95 v_lo
__device__ __nv_bfloat16 g_kv_bf[(size_t)NB * NHEADS * 96 * NPIX];  // 25 MB

// ---------------------------------------------------------------------------
// m16n8k16 bf16 MMA, fp32 accumulate (row.col)
// ---------------------------------------------------------------------------
#define MMA16816(c, a, b0v, b1v)                                              \
    asm volatile(                                                             \
        "mma.sync.aligned.m16n8k16.row.col.f32.bf16.bf16.f32 "                \
        "{%0,%1,%2,%3}, {%4,%5,%6,%7}, {%8,%9}, {%0,%1,%2,%3};"               \
        : "+f"((c)[0]), "+f"((c)[1]), "+f"((c)[2]), "+f"((c)[3])              \
        : "r"((a)[0]), "r"((a)[1]), "r"((a)[2]), "r"((a)[3]),                 \
          "r"(b0v), "r"(b1v))

// Split-pack: hi = bf16(v), lo = bf16(v - hi); element0 in low 16 bits.
__device__ __forceinline__ unsigned pack_hi2(float v0, float v1, unsigned& lo_out) {
    __nv_bfloat162 hh, ll;
    hh.x = __float2bfloat16_rn(v0);
    hh.y = __float2bfloat16_rn(v1);
    ll.x = __float2bfloat16_rn(v0 - __bfloat162float(hh.x));
    ll.y = __float2bfloat16_rn(v1 - __bfloat162float(hh.y));
    lo_out = *(unsigned*)&ll;
    return *(unsigned*)&hh;
}

// Single-instruction pack of 2 floats -> bf16x2 (lo in bits [15:0]).
__device__ __forceinline__ unsigned pack_bf16x2(float lo, float hi) {
    unsigned r;
    asm("cvt.rn.bf16x2.f32 %0, %1, %2;" : "=r"(r) : "f"(hi), "f"(lo));
    return r;
}

// ---------------------------------------------------------------------------
// Tensor-core GEMM + BN:  Out[b][o][p] = BN( sum_c W[o][c] * In[b][c][p] )
// bf16 hi/lo 3-MMA split (fp32-grade). CTA tile 64o x 128p, 8 warps (4o x 2p),
// warp tile 16o x 64p (8 ntiles m16n8k16). K staged per 16-c step with
// register prefetch, single smem buffer.
// Smem layouts (proven conflict-free fragment pattern, stride 24 bf16):
//   Ws[o][c]  64x24  (A frags),   Bs[p][c]  128x24  (B frags)
// If kvbuf != nullptr (qkv GEMM): also emits bf16 hi/lo K/V planes.
// ---------------------------------------------------------------------------
__global__ void __launch_bounds__(256)
gemm_bn_kernel(const float* __restrict__ W,
               const float* __restrict__ In,
               float* __restrict__ Out,
               int M,
               const float* __restrict__ gam,
               const float* __restrict__ bet,
               const float* __restrict__ mu,
               const float* __restrict__ var,
               __nv_bfloat16* __restrict__ kvbuf) {
    __shared__ __align__(16) __nv_bfloat16 Ws_h[64][24], Ws_l[64][24];
    __shared__ __align__(16) __nv_bfloat16 Bs_h[128][24], Bs_l[128][24];

    const int b = blockIdx.z;
    const int oBase = blockIdx.y * 64;
    const int pBase = blockIdx.x * 128;
    const int tid = threadIdx.x;
    const int warp = tid >> 5;
    const int lane = tid & 31;
    const int gr = lane >> 2;
    const int tc = lane & 3;
    const int wo = warp >> 1;        // 0..3  -> o sub-tile
    const int wp = warp & 1;         // 0..1  -> p sub-tile
    const int o0 = wo * 16;
    const int p0 = wp * 64;

    const float* inb = In + (size_t)b * DIMC * NPIX;

    // staging indices
    const int sw_o = tid >> 2;              // W: o row (0..63)
    const int sw_c = (tid & 3) * 4;         // W: c quad base
    const int sb_p = tid & 127;             // In: p col (0..127)
    const int sb_cp = tid >> 7;             // In: c-pair base (0..1)

    float wreg[4];
    float inreg[8];                         // 4 c-pairs

    // ---- prefetch kstep 0 ----
    {
        *(float4*)wreg = *(const float4*)&W[(size_t)(oBase + sw_o) * DIMC + sw_c];
#pragma unroll
        for (int j = 0; j < 4; j++) {
            int c = 2 * (sb_cp + 2 * j);
            inreg[2 * j]     = inb[(size_t)c * NPIX + pBase + sb_p];
            inreg[2 * j + 1] = inb[(size_t)(c + 1) * NPIX + pBase + sb_p];
        }
    }

    float C[8][4];
#pragma unroll
    for (int nt = 0; nt < 8; nt++)
#pragma unroll
        for (int r = 0; r < 4; r++) C[nt][r] = 0.f;

    for (int ks = 0; ks < 16; ks++) {
        // ---- commit staged regs to smem ----
        {
#pragma unroll
            for (int j = 0; j < 2; j++) {
                float v0 = wreg[2 * j], v1 = wreg[2 * j + 1];
                unsigned lo, hi = pack_hi2(v0, v1, lo);
                *(unsigned*)&Ws_h[sw_o][sw_c + 2 * j] = hi;
                *(unsigned*)&Ws_l[sw_o][sw_c + 2 * j] = lo;
            }
#pragma unroll
            for (int j = 0; j < 4; j++) {
                int c = 2 * (sb_cp + 2 * j);
                unsigned lo, hi = pack_hi2(inreg[2 * j], inreg[2 * j + 1], lo);
                *(unsigned*)&Bs_h[sb_p][c] = hi;
                *(unsigned*)&Bs_l[sb_p][c] = lo;
            }
        }
        __syncthreads();

        // ---- prefetch next kstep ----
        if (ks < 15) {
            int k0 = (ks + 1) * 16;
            *(float4*)wreg = *(const float4*)&W[(size_t)(oBase + sw_o) * DIMC + k0 + sw_c];
#pragma unroll
            for (int j = 0; j < 4; j++) {
                int c = k0 + 2 * (sb_cp + 2 * j);
                inreg[2 * j]     = inb[(size_t)c * NPIX + pBase + sb_p];
                inreg[2 * j + 1] = inb[(size_t)(c + 1) * NPIX + pBase + sb_p];
            }
        }

        // ---- compute: A frags then 8 ntiles ----
        unsigned ah[4], al[4];
        ah[0] = *(const unsigned*)&Ws_h[o0 + gr][2 * tc];
        ah[1] = *(const unsigned*)&Ws_h[o0 + gr + 8][2 * tc];
        ah[2] = *(const unsigned*)&Ws_h[o0 + gr][2 * tc + 8];
        ah[3] = *(const unsigned*)&Ws_h[o0 + gr + 8][2 * tc + 8];
        al[0] = *(const unsigned*)&Ws_l[o0 + gr][2 * tc];
        al[1] = *(const unsigned*)&Ws_l[o0 + gr + 8][2 * tc];
        al[2] = *(const unsigned*)&Ws_l[o0 + gr][2 * tc + 8];
        al[3] = *(const unsigned*)&Ws_l[o0 + gr + 8][2 * tc + 8];
#pragma unroll
        for (int nt = 0; nt < 8; nt++) {
            int p = p0 + nt * 8 + gr;
            unsigned bh0 = *(const unsigned*)&Bs_h[p][2 * tc];
            unsigned bh1 = *(const unsigned*)&Bs_h[p][2 * tc + 8];
            unsigned bl0 = *(const unsigned*)&Bs_l[p][2 * tc];
            unsigned bl1 = *(const unsigned*)&Bs_l[p][2 * tc + 8];
            MMA16816(C[nt], ah, bh0, bh1);
            MMA16816(C[nt], ah, bl0, bl1);
            MMA16816(C[nt], al, bh0, bh1);
        }
        __syncthreads();   // all warps done before restage
    }

    // ---- epilogue: BN + store (+ optional kv bf16 plane emission) ----
    const int oG0 = oBase + o0 + gr;
    const int oG1 = oG0 + 8;
    float inv0 = rsqrtf(var[oG0] + EPSV) * gam[oG0];
    float add0 = bet[oG0] - mu[oG0] * inv0;
    float inv1 = rsqrtf(var[oG1] + EPSV) * gam[oG1];
    float add1 = bet[oG1] - mu[oG1] * inv1;

#pragma unroll
    for (int nt = 0; nt < 8; nt++) {
        int p = pBase + p0 + nt * 8 + 2 * tc;
        float2 r0, r1;
        r0.x = C[nt][0] * inv0 + add0;
        r0.y = C[nt][1] * inv0 + add0;
        r1.x = C[nt][2] * inv1 + add1;
        r1.y = C[nt][3] * inv1 + add1;
        *(float2*)&Out[((size_t)b * M + oG0) * NPIX + p] = r0;
        *(float2*)&Out[((size_t)b * M + oG1) * NPIX + p] = r1;

        if (kvbuf != nullptr) {
#pragma unroll
            for (int rr = 0; rr < 2; rr++) {
                int o = rr ? oG1 : oG0;
                float vx = rr ? r1.x : r0.x;
                float vy = rr ? r1.y : r0.y;
                int r64 = o & 63;
                if (r64 >= 16) {
                    int h = o >> 6;
                    int hi_row = (r64 < 32) ? (r64 - 16) : r64;
                    int lo_row = hi_row + ((r64 < 32) ? 16 : 32);
                    unsigned lo, hi = pack_hi2(vx, vy, lo);
                    size_t hbase = (((size_t)b * NHEADS + h) * 96) * NPIX + p;
                    *(unsigned*)&kvbuf[hbase + (size_t)hi_row * NPIX] = hi;
                    *(unsigned*)&kvbuf[hbase + (size_t)lo_row * NPIX] = lo;
                }
            }
        }
    }
}

// ---------------------------------------------------------------------------
// FlashAttention-2, mma.sync bf16, pre-split K/V planes.
// Fragment loads hoisted across the two q-tiles: 96 LDS.32/chunk/warp.
// ---------------------------------------------------------------------------
__global__ void __launch_bounds__(256, 1)
attn_kernel(const float* __restrict__ qkv,
            const __nv_bfloat16* __restrict__ kvbf,
            float* __restrict__ att) {
    __shared__ __align__(16) __nv_bfloat16 Ks_h[64][24];
    __shared__ __align__(16) __nv_bfloat16 Ks_l[64][24];
    __shared__ __align__(16) __nv_bfloat16 Vt_h[32][72];
    __shared__ __align__(16) __nv_bfloat16 Vt_l[32][72];
    __shared__ float Qs[16][256];

    const int blk = blockIdx.x;      // 0..511
    const int bh = blk >> 2;
    const int qq = blk & 3;
    const int b = bh >> 3;
    const int h = bh & 7;
    const float* base = qkv + ((size_t)b * HQKV + h * 64) * NPIX;
    const unsigned* kv32 = (const unsigned*)(kvbf + ((size_t)b * NHEADS + h) * 96 * NPIX);
    float* ob = att + ((size_t)b * DIMC + h * HEADD) * NPIX;

    const int tid = threadIdx.x;
    const int warp = tid >> 5;
    const int lane = tid & 31;
    const int gr = lane >> 2;
    const int tc = lane & 3;
    const int qBase = qq * 256;

    const int kc0 = tid >> 5;
    const int ki0 = tid & 31;
    const int vd0 = tid >> 5;

    unsigned kr[4], vr[8];

    // ---- stage Q (scaled) ----
    for (int idx = tid; idx < 16 * 256; idx += 256) {
        int c = idx >> 8, p = idx & 255;
        Qs[c][p] = base[c * NPIX + qBase + p] * ATTN_SCALE;
    }

    // ---- prefetch chunk 0 ----
#pragma unroll
    for (int j = 0; j < 2; j++) {
        int c = kc0 + j * 8;
        kr[j]     = kv32[(size_t)c * 512 + ki0];
        kr[2 + j] = kv32[(size_t)(16 + c) * 512 + ki0];
    }
#pragma unroll
    for (int j = 0; j < 4; j++) {
        int d = vd0 + j * 8;
        vr[j]     = kv32[(size_t)(32 + d) * 512 + ki0];
        vr[4 + j] = kv32[(size_t)(64 + d) * 512 + ki0];
    }
    __syncthreads();

    // ---- store chunk 0 ----
#pragma unroll
    for (int j = 0; j < 2; j++) {
        int c = kc0 + j * 8;
        __nv_bfloat162 vh = *(__nv_bfloat162*)&kr[j];
        Ks_h[2 * ki0][c] = vh.x;  Ks_h[2 * ki0 + 1][c] = vh.y;
        __nv_bfloat162 vl = *(__nv_bfloat162*)&kr[2 + j];
        Ks_l[2 * ki0][c] = vl.x;  Ks_l[2 * ki0 + 1][c] = vl.y;
    }
#pragma unroll
    for (int j = 0; j < 4; j++) {
        int d = vd0 + j * 8;
        *(unsigned*)&Vt_h[d][2 * ki0] = vr[j];
        *(unsigned*)&Vt_l[d][2 * ki0] = vr[4 + j];
    }
    __syncthreads();

    // ---- Q fragments ----
    unsigned qf[2][2][4];
#pragma unroll
    for (int qt = 0; qt < 2; qt++) {
        int q0 = warp * 32 + qt * 16 + gr;
#pragma unroll
        for (int r = 0; r < 4; r++) {
            int row = q0 + ((r & 1) ? 8 : 0);
            int k0 = 2 * tc + ((r & 2) ? 8 : 0);
            qf[qt][0][r] = pack_hi2(Qs[k0][row], Qs[k0 + 1][row], qf[qt][1][r]);
        }
    }

    float m[2][2], l[2][2];
    float O[2][4][4];
#pragma unroll
    for (int qt = 0; qt < 2; qt++) {
        m[qt][0] = -1e30f; m[qt][1] = -1e30f;
        l[qt][0] = 0.f;    l[qt][1] = 0.f;
#pragma unroll
        for (int dt = 0; dt < 4; dt++)
#pragma unroll
            for (int r = 0; r < 4; r++) O[qt][dt][r] = 0.f;
    }

    for (int kb = 0; kb < NPIX; kb += 64) {
        const bool more = (kb + 64 < NPIX);
        if (more) {
            const int kb2 = (kb + 64) >> 1;
#pragma unroll
            for (int j = 0; j < 2; j++) {
                int c = kc0 + j * 8;
                kr[j]     = kv32[(size_t)c * 512 + kb2 + ki0];
                kr[2 + j] = kv32[(size_t)(16 + c) * 512 + kb2 + ki0];
            }
#pragma unroll
            for (int j = 0; j < 4; j++) {
                int d = vd0 + j * 8;
                vr[j]     = kv32[(size_t)(32 + d) * 512 + kb2 + ki0];
                vr[4 + j] = kv32[(size_t)(64 + d) * 512 + kb2 + ki0];
            }
        }

        // ---- scores for BOTH q-tiles, B frags loaded once per ntile ----
        float S[2][8][4];
#pragma unroll
        for (int nt = 0; nt < 8; nt++) {
            const int krow = nt * 8 + gr;
            unsigned bh0 = *(const unsigned*)&Ks_h[krow][2 * tc];
            unsigned bh1 = *(const unsigned*)&Ks_h[krow][2 * tc + 8];
            unsigned bl0 = *(const unsigned*)&Ks_l[krow][2 * tc];
            unsigned bl1 = *(const unsigned*)&Ks_l[krow][2 * tc + 8];
#pragma unroll
            for (int qt = 0; qt < 2; qt++) {
                S[qt][nt][0] = 0.f; S[qt][nt][1] = 0.f;
                S[qt][nt][2] = 0.f; S[qt][nt][3] = 0.f;
                MMA16816(S[qt][nt], qf[qt][0], bh0, bh1);
                MMA16816(S[qt][nt], qf[qt][0], bl0, bl1);
                MMA16816(S[qt][nt], qf[qt][1], bh0, bh1);
            }
        }

        // ---- online softmax per q-tile ----
        float al_[2][2];
#pragma unroll
        for (int qt = 0; qt < 2; qt++) {
            float mx0 = -1e30f, mx1 = -1e30f;
#pragma unroll
            for (int nt = 0; nt < 8; nt++) {
                mx0 = fmaxf(mx0, fmaxf(S[qt][nt][0], S[qt][nt][1]));
                mx1 = fmaxf(mx1, fmaxf(S[qt][nt][2], S[qt][nt][3]));
            }
            mx0 = fmaxf(mx0, __shfl_xor_sync(0xffffffffu, mx0, 1));
            mx0 = fmaxf(mx0, __shfl_xor_sync(0xffffffffu, mx0, 2));
            mx1 = fmaxf(mx1, __shfl_xor_sync(0xffffffffu, mx1, 1));
            mx1 = fmaxf(mx1, __shfl_xor_sync(0xffffffffu, mx1, 2));

            float nm0 = fmaxf(m[qt][0], mx0);
            float nm1 = fmaxf(m[qt][1], mx1);
            float a0 = __expf(m[qt][0] - nm0);
            float a1 = __expf(m[qt][1] - nm1);
            m[qt][0] = nm0; m[qt][1] = nm1;
            al_[qt][0] = a0; al_[qt][1] = a1;

            float ls0 = 0.f, ls1 = 0.f;
#pragma unroll
            for (int nt = 0; nt < 8; nt++) {
                S[qt][nt][0] = __expf(S[qt][nt][0] - nm0);
                S[qt][nt][1] = __expf(S[qt][nt][1] - nm0);
                S[qt][nt][2] = __expf(S[qt][nt][2] - nm1);
                S[qt][nt][3] = __expf(S[qt][nt][3] - nm1);
                ls0 += S[qt][nt][0] + S[qt][nt][1];
                ls1 += S[qt][nt][2] + S[qt][nt][3];
            }
            ls0 += __shfl_xor_sync(0xffffffffu, ls0, 1);
            ls0 += __shfl_xor_sync(0xffffffffu, ls0, 2);
            ls1 += __shfl_xor_sync(0xffffffffu, ls1, 1);
            ls1 += __shfl_xor_sync(0xffffffffu, ls1, 2);
            l[qt][0] = l[qt][0] * a0 + ls0;
            l[qt][1] = l[qt][1] * a1 + ls1;

#pragma unroll
            for (int dt = 0; dt < 4; dt++) {
                O[qt][dt][0] *= a0; O[qt][dt][1] *= a0;
                O[qt][dt][2] *= a1; O[qt][dt][3] *= a1;
            }
        }

        // ---- AV: V frags loaded once per (ks,dt), both q-tiles ----
#pragma unroll
        for (int ks = 0; ks < 4; ks++) {
            unsigned ph[2][4];
#pragma unroll
            for (int qt = 0; qt < 2; qt++) {
                ph[qt][0] = pack_bf16x2(S[qt][2 * ks][0],     S[qt][2 * ks][1]);
                ph[qt][1] = pack_bf16x2(S[qt][2 * ks][2],     S[qt][2 * ks][3]);
                ph[qt][2] = pack_bf16x2(S[qt][2 * ks + 1][0], S[qt][2 * ks + 1][1]);
                ph[qt][3] = pack_bf16x2(S[qt][2 * ks + 1][2], S[qt][2 * ks + 1][3]);
            }
#pragma unroll
            for (int dt = 0; dt < 4; dt++) {
                const int dr = dt * 8 + gr;
                const int kc = ks * 16 + 2 * tc;
                unsigned vh0 = *(const unsigned*)&Vt_h[dr][kc];
                unsigned vh1 = *(const unsigned*)&Vt_h[dr][kc + 8];
                unsigned vl0 = *(const unsigned*)&Vt_l[dr][kc];
                unsigned vl1 = *(const unsigned*)&Vt_l[dr][kc + 8];
                MMA16816(O[0][dt], ph[0], vh0, vh1);
                MMA16816(O[0][dt], ph[0], vl0, vl1);
                MMA16816(O[1][dt], ph[1], vh0, vh1);
                MMA16816(O[1][dt], ph[1], vl0, vl1);
            }
        }

        if (more) {
            __syncthreads();
#pragma unroll
            for (int j = 0; j < 2; j++) {
                int c = kc0 + j * 8;
                __nv_bfloat162 vh = *(__nv_bfloat162*)&kr[j];
                Ks_h[2 * ki0][c] = vh.x;  Ks_h[2 * ki0 + 1][c] = vh.y;
                __nv_bfloat162 vl = *(__nv_bfloat162*)&kr[2 + j];
                Ks_l[2 * ki0][c] = vl.x;  Ks_l[2 * ki0 + 1][c] = vl.y;
            }
#pragma unroll
            for (int j = 0; j < 4; j++) {
                int d = vd0 + j * 8;
                *(unsigned*)&Vt_h[d][2 * ki0] = vr[j];
                *(unsigned*)&Vt_l[d][2 * ki0] = vr[4 + j];
            }
            __syncthreads();
        }
    }

    // ---- epilogue ----
#pragma unroll
    for (int qt = 0; qt < 2; qt++) {
        float r0 = 1.f / l[qt][0];
        float r1 = 1.f / l[qt][1];
        int q0 = qBase + warp * 32 + qt * 16 + gr;
        int q1 = q0 + 8;
#pragma unroll
        for (int dt = 0; dt < 4; dt++) {
            int d = dt * 8 + 2 * tc;
            ob[(size_t)d * NPIX + q0]       = O[qt][dt][0] * r0;
            ob[(size_t)(d + 1) * NPIX + q0] = O[qt][dt][1] * r0;
            ob[(size_t)d * NPIX + q1]       = O[qt][dt][2] * r1;
            ob[(size_t)(d + 1) * NPIX + q1] = O[qt][dt][3] * r1;
        }
    }
}

// ---------------------------------------------------------------------------
// Depthwise 3x3 conv on v_img + BN, added into attended buffer in-place.
// ---------------------------------------------------------------------------
__global__ void pos_conv_kernel(const float* __restrict__ qkv,
                                float* __restrict__ att,
                                const float* __restrict__ wpos,
                                const float* __restrict__ gam,
                                const float* __restrict__ bet,
                                const float* __restrict__ mu,
                                const float* __restrict__ var) {
    int idx = blockIdx.x * blockDim.x + threadIdx.x;
    if (idx >= NB * DIMC * NPIX) return;
    int p = idx & 1023;
    int ch = (idx >> 10) & 255;
    int b = idx >> 18;
    int y = p >> 5, x = p & 31;
    int o = ((ch >> 5) * 64) + 32 + (ch & 31);
    const float* vrow = qkv + ((size_t)b * HQKV + o) * NPIX;
    const float* wp = wpos + ch * 9;

    float acc = 0.f;
#pragma unroll
    for (int dy = 0; dy < 3; dy++) {
        int yy = y + dy - 1;
        if (yy < 0 || yy > 31) continue;
#pragma unroll
        for (int dx = 0; dx < 3; dx++) {
            int xx = x + dx - 1;
            if (xx < 0 || xx > 31) continue;
            acc += vrow[yy * 32 + xx] * wp[dy * 3 + dx];
        }
    }
    float inv = rsqrtf(var[ch] + EPSV) * gam[ch];
    att[idx] += acc * inv + (bet[ch] - mu[ch] * inv);
}

// ---------------------------------------------------------------------------
extern "C" void kernel_launch(void* const* d_in, const int* in_sizes, int n_in,
                              void* d_out, int out_size) {
    const float* x      = (const float*)d_in[0];
    const float* w_qkv  = (const float*)d_in[1];
    const float* g_qkv  = (const float*)d_in[2];
    const float* b_qkv  = (const float*)d_in[3];
    const float* m_qkv  = (const float*)d_in[4];
    const float* v_qkv  = (const float*)d_in[5];
    const float* w_pos  = (const float*)d_in[6];
    const float* g_pos  = (const float*)d_in[7];
    const float* b_pos  = (const float*)d_in[8];
    const float* m_pos  = (const float*)d_in[9];
    const float* v_pos  = (const float*)d_in[10];
    const float* w_proj = (const float*)d_in[11];
    const float* g_proj = (const float*)d_in[12];
    const float* b_proj = (const float*)d_in[13];
    const float* m_proj = (const float*)d_in[14];
    const float* v_proj = (const float*)d_in[15];
    float* out = (float*)d_out;

    float* qkv_buf = nullptr;
    float* att_buf = nullptr;
    __nv_bfloat16* kv_bf = nullptr;
    cudaGetSymbolAddress((void**)&qkv_buf, g_qkv_buf);
    cudaGetSymbolAddress((void**)&att_buf, g_att_buf);
    cudaGetSymbolAddress((void**)&kv_bf, g_kv_bf);

    // 1) QKV GEMM + BN (tensor-core) + bf16 hi/lo K/V plane emission
    gemm_bn_kernel<<<dim3(NPIX / 128, HQKV / 64, NB), 256>>>(
        w_qkv, x, qkv_buf, HQKV, g_qkv, b_qkv, m_qkv, v_qkv, kv_bf);

    // 2) Attention -> att_buf
    attn_kernel<<<512, 256>>>(qkv_buf, kv_bf, att_buf);

    // 3) Depthwise conv + BN, add into att_buf
    pos_conv_kernel<<<(NB * DIMC * NPIX) / 256, 256>>>(
        qkv_buf, att_buf, w_pos, g_pos, b_pos, m_pos, v_pos);

    // 4) Proj GEMM + BN (tensor-core) -> d_out
    gemm_bn_kernel<<<dim3(NPIX / 128, DIMC / 64, NB), 256>>>(
        w_proj, att_buf, out, DIMC, g_proj, b_proj, m_proj, v_proj, nullptr);
}

// round 9
// speedup vs baseline: 2.5640x; 1.1571x over previous
#include <cuda_runtime.h>
#include <cuda_bf16.h>
#include <math.h>

#define DIMC 256
#define NHEADS 8
#define HEADD 32
#define KEYD 16
#define HQKV 512
#define NB 16
#define NPIX 1024
#define EPSV 1e-5f
// score scale folded with log2(e): softmax computed in exp2 domain
#define ATTN_SCALE_LOG2 (0.25f * 1.44269504088896f)

// Scratch (allocation-free rule: __device__ globals)
__device__ float g_qkv_buf[(size_t)NB * HQKV * NPIX];   // 33.5 MB: qkv[b][o][p]
__device__ float g_att_buf[(size_t)NB * DIMC * NPIX];   // 16.8 MB
// K/V pre-split bf16 planes per (b,h): rows 0-15 k_hi, 16-31 k_lo, 32-63 v_hi
__device__ __nv_bfloat16 g_kv_bf[(size_t)NB * NHEADS * 96 * NPIX];

// ---------------------------------------------------------------------------
#define MMA16816(c, a, b0v, b1v)                                              \
    asm volatile(                                                             \
        "mma.sync.aligned.m16n8k16.row.col.f32.bf16.bf16.f32 "                \
        "{%0,%1,%2,%3}, {%4,%5,%6,%7}, {%8,%9}, {%0,%1,%2,%3};"               \
        : "+f"((c)[0]), "+f"((c)[1]), "+f"((c)[2]), "+f"((c)[3])              \
        : "r"((a)[0]), "r"((a)[1]), "r"((a)[2]), "r"((a)[3]),                 \
          "r"(b0v), "r"(b1v))

// Split-pack: hi = bf16(v), lo = bf16(v - hi); element0 in low 16 bits.
__device__ __forceinline__ unsigned pack_hi2(float v0, float v1, unsigned& lo_out) {
    __nv_bfloat162 hh, ll;
    hh.x = __float2bfloat16_rn(v0);
    hh.y = __float2bfloat16_rn(v1);
    ll.x = __float2bfloat16_rn(v0 - __bfloat162float(hh.x));
    ll.y = __float2bfloat16_rn(v1 - __bfloat162float(hh.y));
    lo_out = *(unsigned*)&ll;
    return *(unsigned*)&hh;
}

// Single-instruction pack of 2 floats -> bf16x2 (first arg in bits [15:0]).
__device__ __forceinline__ unsigned pack_bf16x2(float lo, float hi) {
    unsigned r;
    asm("cvt.rn.bf16x2.f32 %0, %1, %2;" : "=r"(r) : "f"(hi), "f"(lo));
    return r;
}

__device__ __forceinline__ float exp2a(float x) {
    float y;
    asm("ex2.approx.f32 %0, %1;" : "=f"(y) : "f"(x));
    return y;
}

// ---------------------------------------------------------------------------
// Tensor-core GEMM + BN, double-buffered smem (1 sync/kstep), 2 CTAs/SM.
//   Out[b][o][p] = BN( sum_c W[o][c] * In[b][c][p] )
// CTA tile 64o x 128p, 8 warps (4o x 2p), warp tile 16o x 64p.
// bf16 hi/lo 3-MMA split (fp32-grade).
// If kvbuf != nullptr: emits bf16 k hi/lo and v hi planes.
// ---------------------------------------------------------------------------
__global__ void __launch_bounds__(256, 2)
gemm_bn_kernel(const float* __restrict__ W,
               const float* __restrict__ In,
               float* __restrict__ Out,
               int M,
               const float* __restrict__ gam,
               const float* __restrict__ bet,
               const float* __restrict__ mu,
               const float* __restrict__ var,
               __nv_bfloat16* __restrict__ kvbuf) {
    __shared__ __align__(16) __nv_bfloat16 Ws_h[2][64][24], Ws_l[2][64][24];
    __shared__ __align__(16) __nv_bfloat16 Bs_h[2][128][24], Bs_l[2][128][24];

    const int b = blockIdx.z;
    const int oBase = blockIdx.y * 64;
    const int pBase = blockIdx.x * 128;
    const int tid = threadIdx.x;
    const int warp = tid >> 5;
    const int lane = tid & 31;
    const int gr = lane >> 2;
    const int tc = lane & 3;
    const int o0 = (warp >> 1) * 16;
    const int p0 = (warp & 1) * 64;

    const float* inb = In + (size_t)b * DIMC * NPIX;

    const int sw_o = tid >> 2;
    const int sw_c = (tid & 3) * 4;
    const int sb_p = tid & 127;
    const int sb_cp = tid >> 7;

    float wreg[4];
    float inreg[8];

    // ---- prefetch kstep 0 ----
    *(float4*)wreg = *(const float4*)&W[(size_t)(oBase + sw_o) * DIMC + sw_c];
#pragma unroll
    for (int j = 0; j < 4; j++) {
        int c = 2 * (sb_cp + 2 * j);
        inreg[2 * j]     = inb[(size_t)c * NPIX + pBase + sb_p];
        inreg[2 * j + 1] = inb[(size_t)(c + 1) * NPIX + pBase + sb_p];
    }
    // ---- commit kstep 0 to buffer 0 ----
#pragma unroll
    for (int j = 0; j < 2; j++) {
        unsigned lo, hi = pack_hi2(wreg[2 * j], wreg[2 * j + 1], lo);
        *(unsigned*)&Ws_h[0][sw_o][sw_c + 2 * j] = hi;
        *(unsigned*)&Ws_l[0][sw_o][sw_c + 2 * j] = lo;
    }
#pragma unroll
    for (int j = 0; j < 4; j++) {
        int c = 2 * (sb_cp + 2 * j);
        unsigned lo, hi = pack_hi2(inreg[2 * j], inreg[2 * j + 1], lo);
        *(unsigned*)&Bs_h[0][sb_p][c] = hi;
        *(unsigned*)&Bs_l[0][sb_p][c] = lo;
    }
    __syncthreads();

    float C[8][4];
#pragma unroll
    for (int nt = 0; nt < 8; nt++)
#pragma unroll
        for (int r = 0; r < 4; r++) C[nt][r] = 0.f;

    for (int ks = 0; ks < 16; ks++) {
        const int cur = ks & 1;
        // ---- prefetch next kstep (overlaps compute) ----
        if (ks < 15) {
            int k0 = (ks + 1) * 16;
            *(float4*)wreg = *(const float4*)&W[(size_t)(oBase + sw_o) * DIMC + k0 + sw_c];
#pragma unroll
            for (int j = 0; j < 4; j++) {
                int c = k0 + 2 * (sb_cp + 2 * j);
                inreg[2 * j]     = inb[(size_t)c * NPIX + pBase + sb_p];
                inreg[2 * j + 1] = inb[(size_t)(c + 1) * NPIX + pBase + sb_p];
            }
        }

        // ---- compute from buffer cur ----
        unsigned ah[4], al[4];
        ah[0] = *(const unsigned*)&Ws_h[cur][o0 + gr][2 * tc];
        ah[1] = *(const unsigned*)&Ws_h[cur][o0 + gr + 8][2 * tc];
        ah[2] = *(const unsigned*)&Ws_h[cur][o0 + gr][2 * tc + 8];
        ah[3] = *(const unsigned*)&Ws_h[cur][o0 + gr + 8][2 * tc + 8];
        al[0] = *(const unsigned*)&Ws_l[cur][o0 + gr][2 * tc];
        al[1] = *(const unsigned*)&Ws_l[cur][o0 + gr + 8][2 * tc];
        al[2] = *(const unsigned*)&Ws_l[cur][o0 + gr][2 * tc + 8];
        al[3] = *(const unsigned*)&Ws_l[cur][o0 + gr + 8][2 * tc + 8];
#pragma unroll
        for (int nt = 0; nt < 8; nt++) {
            int p = p0 + nt * 8 + gr;
            unsigned bh0 = *(const unsigned*)&Bs_h[cur][p][2 * tc];
            unsigned bh1 = *(const unsigned*)&Bs_h[cur][p][2 * tc + 8];
            unsigned bl0 = *(const unsigned*)&Bs_l[cur][p][2 * tc];
            unsigned bl1 = *(const unsigned*)&Bs_l[cur][p][2 * tc + 8];
            MMA16816(C[nt], ah, bh0, bh1);
            MMA16816(C[nt], ah, bl0, bl1);
            MMA16816(C[nt], al, bh0, bh1);
        }

        // ---- commit prefetched regs to other buffer ----
        if (ks < 15) {
            const int nxt = cur ^ 1;
#pragma unroll
            for (int j = 0; j < 2; j++) {
                unsigned lo, hi = pack_hi2(wreg[2 * j], wreg[2 * j + 1], lo);
                *(unsigned*)&Ws_h[nxt][sw_o][sw_c + 2 * j] = hi;
                *(unsigned*)&Ws_l[nxt][sw_o][sw_c + 2 * j] = lo;
            }
#pragma unroll
            for (int j = 0; j < 4; j++) {
                int c = 2 * (sb_cp + 2 * j);
                unsigned lo, hi = pack_hi2(inreg[2 * j], inreg[2 * j + 1], lo);
                *(unsigned*)&Bs_h[nxt][sb_p][c] = hi;
                *(unsigned*)&Bs_l[nxt][sb_p][c] = lo;
            }
            __syncthreads();
        }
    }

    // ---- epilogue: BN + store (+ optional kv bf16 plane emission) ----
    const int oG0 = oBase + o0 + gr;
    const int oG1 = oG0 + 8;
    float inv0 = rsqrtf(var[oG0] + EPSV) * gam[oG0];
    float add0 = bet[oG0] - mu[oG0] * inv0;
    float inv1 = rsqrtf(var[oG1] + EPSV) * gam[oG1];
    float add1 = bet[oG1] - mu[oG1] * inv1;

#pragma unroll
    for (int nt = 0; nt < 8; nt++) {
        int p = pBase + p0 + nt * 8 + 2 * tc;
        float2 r0, r1;
        r0.x = C[nt][0] * inv0 + add0;
        r0.y = C[nt][1] * inv0 + add0;
        r1.x = C[nt][2] * inv1 + add1;
        r1.y = C[nt][3] * inv1 + add1;
        *(float2*)&Out[((size_t)b * M + oG0) * NPIX + p] = r0;
        *(float2*)&Out[((size_t)b * M + oG1) * NPIX + p] = r1;

        if (kvbuf != nullptr) {
#pragma unroll
            for (int rr = 0; rr < 2; rr++) {
                int o = rr ? oG1 : oG0;
                float vx = rr ? r1.x : r0.x;
                float vy = rr ? r1.y : r0.y;
                int r64 = o & 63;
                if (r64 >= 16) {
                    int h = o >> 6;
                    size_t hbase = (((size_t)b * NHEADS + h) * 96) * NPIX + p;
                    if (r64 < 32) {   // k: hi + lo planes
                        unsigned lo, hi = pack_hi2(vx, vy, lo);
                        *(unsigned*)&kvbuf[hbase + (size_t)(r64 - 16) * NPIX] = hi;
                        *(unsigned*)&kvbuf[hbase + (size_t)r64 * NPIX] = lo;
                    } else {          // v: hi plane only
                        unsigned hi = pack_bf16x2(vx, vy);
                        *(unsigned*)&kvbuf[hbase + (size_t)r64 * NPIX] = hi;
                    }
                }
            }
        }
    }
}

// ---------------------------------------------------------------------------
// FlashAttention-2, mma.sync bf16. Double-buffered K/V smem (1 sync/chunk).
// QK: 2 MMAs (Q bf16-hi x K hi/lo). AV: 1 MMA (P-hi x V-hi). exp2 softmax.
// ---------------------------------------------------------------------------
__global__ void __launch_bounds__(256, 1)
attn_kernel(const float* __restrict__ qkv,
            const __nv_bfloat16* __restrict__ kvbf,
            float* __restrict__ att) {
    __shared__ __align__(16) __nv_bfloat16 Ks_h[2][64][24];
    __shared__ __align__(16) __nv_bfloat16 Ks_l[2][64][24];
    __shared__ __align__(16) __nv_bfloat16 Vt_h[2][32][72];
    __shared__ float Qs[16][256];

    const int blk = blockIdx.x;      // 0..511
    const int bh = blk >> 2;
    const int qq = blk & 3;
    const int b = bh >> 3;
    const int h = bh & 7;
    const float* base = qkv + ((size_t)b * HQKV + h * 64) * NPIX;
    const unsigned* kv32 = (const unsigned*)(kvbf + ((size_t)b * NHEADS + h) * 96 * NPIX);
    float* ob = att + ((size_t)b * DIMC + h * HEADD) * NPIX;

    const int tid = threadIdx.x;
    const int warp = tid >> 5;
    const int lane = tid & 31;
    const int gr = lane >> 2;
    const int tc = lane & 3;
    const int qBase = qq * 256;

    const int kc0 = tid >> 5;        // K row base (0..7)
    const int ki0 = tid & 31;        // u32 col
    const int vd0 = tid >> 5;        // V row base

    unsigned kr[4], vr[4];

    // ---- stage Q (scaled into exp2 domain) ----
    for (int idx = tid; idx < 16 * 256; idx += 256) {
        int c = idx >> 8, p = idx & 255;
        Qs[c][p] = base[c * NPIX + qBase + p] * ATTN_SCALE_LOG2;
    }

    // ---- prefetch + commit chunk 0 to buffer 0 ----
#pragma unroll
    for (int j = 0; j < 2; j++) {
        int c = kc0 + j * 8;
        kr[j]     = kv32[(size_t)c * 512 + ki0];
        kr[2 + j] = kv32[(size_t)(16 + c) * 512 + ki0];
    }
#pragma unroll
    for (int j = 0; j < 4; j++) {
        int d = vd0 + j * 8;
        vr[j] = kv32[(size_t)(32 + d) * 512 + ki0];
    }
#pragma unroll
    for (int j = 0; j < 2; j++) {
        int c = kc0 + j * 8;
        __nv_bfloat162 vh = *(__nv_bfloat162*)&kr[j];
        Ks_h[0][2 * ki0][c] = vh.x;  Ks_h[0][2 * ki0 + 1][c] = vh.y;
        __nv_bfloat162 vl = *(__nv_bfloat162*)&kr[2 + j];
        Ks_l[0][2 * ki0][c] = vl.x;  Ks_l[0][2 * ki0 + 1][c] = vl.y;
    }
#pragma unroll
    for (int j = 0; j < 4; j++)
        *(unsigned*)&Vt_h[0][vd0 + j * 8][2 * ki0] = vr[j];
    __syncthreads();

    // ---- Q fragments (bf16 hi only) ----
    unsigned qf[2][4];
#pragma unroll
    for (int qt = 0; qt < 2; qt++) {
        int q0 = warp * 32 + qt * 16 + gr;
#pragma unroll
        for (int r = 0; r < 4; r++) {
            int row = q0 + ((r & 1) ? 8 : 0);
            int k0 = 2 * tc + ((r & 2) ? 8 : 0);
            qf[qt][r] = pack_bf16x2(Qs[k0][row], Qs[k0 + 1][row]);
        }
    }

    float m[2][2], l[2][2];
    float O[2][4][4];
#pragma unroll
    for (int qt = 0; qt < 2; qt++) {
        m[qt][0] = -1e30f; m[qt][1] = -1e30f;
        l[qt][0] = 0.f;    l[qt][1] = 0.f;
#pragma unroll
        for (int dt = 0; dt < 4; dt++)
#pragma unroll
            for (int r = 0; r < 4; r++) O[qt][dt][r] = 0.f;
    }

    for (int kb = 0; kb < 16; kb++) {
        const int cur = kb & 1;
        const bool more = (kb < 15);
        // ---- prefetch next chunk into regs (overlaps compute) ----
        if (more) {
            const int off = (kb + 1) * 32;
#pragma unroll
            for (int j = 0; j < 2; j++) {
                int c = kc0 + j * 8;
                kr[j]     = kv32[(size_t)c * 512 + off + ki0];
                kr[2 + j] = kv32[(size_t)(16 + c) * 512 + off + ki0];
            }
#pragma unroll
            for (int j = 0; j < 4; j++) {
                int d = vd0 + j * 8;
                vr[j] = kv32[(size_t)(32 + d) * 512 + off + ki0];
            }
        }

        // ---- scores for both q-tiles ----
        float S[2][8][4];
#pragma unroll
        for (int nt = 0; nt < 8; nt++) {
            const int krow = nt * 8 + gr;
            unsigned bh0 = *(const unsigned*)&Ks_h[cur][krow][2 * tc];
            unsigned bh1 = *(const unsigned*)&Ks_h[cur][krow][2 * tc + 8];
            unsigned bl0 = *(const unsigned*)&Ks_l[cur][krow][2 * tc];
            unsigned bl1 = *(const unsigned*)&Ks_l[cur][krow][2 * tc + 8];
#pragma unroll
            for (int qt = 0; qt < 2; qt++) {
                S[qt][nt][0] = 0.f; S[qt][nt][1] = 0.f;
                S[qt][nt][2] = 0.f; S[qt][nt][3] = 0.f;
                MMA16816(S[qt][nt], qf[qt], bh0, bh1);
                MMA16816(S[qt][nt], qf[qt], bl0, bl1);
            }
        }

        // ---- online softmax (exp2 domain) ----
#pragma unroll
        for (int qt = 0; qt < 2; qt++) {
            float mx0 = -1e30f, mx1 = -1e30f;
#pragma unroll
            for (int nt = 0; nt < 8; nt++) {
                mx0 = fmaxf(mx0, fmaxf(S[qt][nt][0], S[qt][nt][1]));
                mx1 = fmaxf(mx1, fmaxf(S[qt][nt][2], S[qt][nt][3]));
            }
            mx0 = fmaxf(mx0, __shfl_xor_sync(0xffffffffu, mx0, 1));
            mx0 = fmaxf(mx0, __shfl_xor_sync(0xffffffffu, mx0, 2));
            mx1 = fmaxf(mx1, __shfl_xor_sync(0xffffffffu, mx1, 1));
            mx1 = fmaxf(mx1, __shfl_xor_sync(0xffffffffu, mx1, 2));

            float nm0 = fmaxf(m[qt][0], mx0);
            float nm1 = fmaxf(m[qt][1], mx1);
            float a0 = exp2a(m[qt][0] - nm0);
            float a1 = exp2a(m[qt][1] - nm1);
            m[qt][0] = nm0; m[qt][1] = nm1;

            float ls0 = 0.f, ls1 = 0.f;
#pragma unroll
            for (int nt = 0; nt < 8; nt++) {
                S[qt][nt][0] = exp2a(S[qt][nt][0] - nm0);
                S[qt][nt][1] = exp2a(S[qt][nt][1] - nm0);
                S[qt][nt][2] = exp2a(S[qt][nt][2] - nm1);
                S[qt][nt][3] = exp2a(S[qt][nt][3] - nm1);
                ls0 += S[qt][nt][0] + S[qt][nt][1];
                ls1 += S[qt][nt][2] + S[qt][nt][3];
            }
            ls0 += __shfl_xor_sync(0xffffffffu, ls0, 1);
            ls0 += __shfl_xor_sync(0xffffffffu, ls0, 2);
            ls1 += __shfl_xor_sync(0xffffffffu, ls1, 1);
            ls1 += __shfl_xor_sync(0xffffffffu, ls1, 2);
            l[qt][0] = l[qt][0] * a0 + ls0;
            l[qt][1] = l[qt][1] * a1 + ls1;

#pragma unroll
            for (int dt = 0; dt < 4; dt++) {
                O[qt][dt][0] *= a0; O[qt][dt][1] *= a0;
                O[qt][dt][2] *= a1; O[qt][dt][3] *= a1;
            }
        }

        // ---- AV: 1 MMA per (ks,dt,qt) ----
#pragma unroll
        for (int ks = 0; ks < 4; ks++) {
            unsigned ph[2][4];
#pragma unroll
            for (int qt = 0; qt < 2; qt++) {
                ph[qt][0] = pack_bf16x2(S[qt][2 * ks][0],     S[qt][2 * ks][1]);
                ph[qt][1] = pack_bf16x2(S[qt][2 * ks][2],     S[qt][2 * ks][3]);
                ph[qt][2] = pack_bf16x2(S[qt][2 * ks + 1][0], S[qt][2 * ks + 1][1]);
                ph[qt][3] = pack_bf16x2(S[qt][2 * ks + 1][2], S[qt][2 * ks + 1][3]);
            }
#pragma unroll
            for (int dt = 0; dt < 4; dt++) {
                const int dr = dt * 8 + gr;
                const int kc = ks * 16 + 2 * tc;
                unsigned vh0 = *(const unsigned*)&Vt_h[cur][dr][kc];
                unsigned vh1 = *(const unsigned*)&Vt_h[cur][dr][kc + 8];
                MMA16816(O[0][dt], ph[0], vh0, vh1);
                MMA16816(O[1][dt], ph[1], vh0, vh1);
            }
        }

        // ---- commit prefetched chunk to other buffer, single sync ----
        if (more) {
            const int nxt = cur ^ 1;
#pragma unroll
            for (int j = 0; j < 2; j++) {
                int c = kc0 + j * 8;
                __nv_bfloat162 vh = *(__nv_bfloat162*)&kr[j];
                Ks_h[nxt][2 * ki0][c] = vh.x;  Ks_h[nxt][2 * ki0 + 1][c] = vh.y;
                __nv_bfloat162 vl = *(__nv_bfloat162*)&kr[2 + j];
                Ks_l[nxt][2 * ki0][c] = vl.x;  Ks_l[nxt][2 * ki0 + 1][c] = vl.y;
            }
#pragma unroll
            for (int j = 0; j < 4; j++)
                *(unsigned*)&Vt_h[nxt][vd0 + j * 8][2 * ki0] = vr[j];
            __syncthreads();
        }
    }

    // ---- epilogue ----
#pragma unroll
    for (int qt = 0; qt < 2; qt++) {
        float r0 = 1.f / l[qt][0];
        float r1 = 1.f / l[qt][1];
        int q0 = qBase + warp * 32 + qt * 16 + gr;
        int q1 = q0 + 8;
#pragma unroll
        for (int dt = 0; dt < 4; dt++) {
            int d = dt * 8 + 2 * tc;
            ob[(size_t)d * NPIX + q0]       = O[qt][dt][0] * r0;
            ob[(size_t)(d + 1) * NPIX + q0] = O[qt][dt][1] * r0;
            ob[(size_t)d * NPIX + q1]       = O[qt][dt][2] * r1;
            ob[(size_t)(d + 1) * NPIX + q1] = O[qt][dt][3] * r1;
        }
    }
}

// ---------------------------------------------------------------------------
// Depthwise 3x3 conv on v_img + BN, added into attended buffer in-place.
// ---------------------------------------------------------------------------
__global__ void pos_conv_kernel(const float* __restrict__ qkv,
                                float* __restrict__ att,
                                const float* __restrict__ wpos,
                                const float* __restrict__ gam,
                                const float* __restrict__ bet,
                                const float* __restrict__ mu,
                                const float* __restrict__ var) {
    int idx = blockIdx.x * blockDim.x + threadIdx.x;
    if (idx >= NB * DIMC * NPIX) return;
    int p = idx & 1023;
    int ch = (idx >> 10) & 255;
    int b = idx >> 18;
    int y = p >> 5, x = p & 31;
    int o = ((ch >> 5) * 64) + 32 + (ch & 31);
    const float* vrow = qkv + ((size_t)b * HQKV + o) * NPIX;
    const float* wp = wpos + ch * 9;

    float acc = 0.f;
#pragma unroll
    for (int dy = 0; dy < 3; dy++) {
        int yy = y + dy - 1;
        if (yy < 0 || yy > 31) continue;
#pragma unroll
        for (int dx = 0; dx < 3; dx++) {
            int xx = x + dx - 1;
            if (xx < 0 || xx > 31) continue;
            acc += vrow[yy * 32 + xx] * wp[dy * 3 + dx];
        }
    }
    float inv = rsqrtf(var[ch] + EPSV) * gam[ch];
    att[idx] += acc * inv + (bet[ch] - mu[ch] * inv);
}

// ---------------------------------------------------------------------------
extern "C" void kernel_launch(void* const* d_in, const int* in_sizes, int n_in,
                              void* d_out, int out_size) {
    const float* x      = (const float*)d_in[0];
    const float* w_qkv  = (const float*)d_in[1];
    const float* g_qkv  = (const float*)d_in[2];
    const float* b_qkv  = (const float*)d_in[3];
    const float* m_qkv  = (const float*)d_in[4];
    const float* v_qkv  = (const float*)d_in[5];
    const float* w_pos  = (const float*)d_in[6];
    const float* g_pos  = (const float*)d_in[7];
    const float* b_pos  = (const float*)d_in[8];
    const float* m_pos  = (const float*)d_in[9];
    const float* v_pos  = (const float*)d_in[10];
    const float* w_proj = (const float*)d_in[11];
    const float* g_proj = (const float*)d_in[12];
    const float* b_proj = (const float*)d_in[13];
    const float* m_proj = (const float*)d_in[14];
    const float* v_proj = (const float*)d_in[15];
    float* out = (float*)d_out;

    float* qkv_buf = nullptr;
    float* att_buf = nullptr;
    __nv_bfloat16* kv_bf = nullptr;
    cudaGetSymbolAddress((void**)&qkv_buf, g_qkv_buf);
    cudaGetSymbolAddress((void**)&att_buf, g_att_buf);
    cudaGetSymbolAddress((void**)&kv_bf, g_kv_bf);

    // 1) QKV GEMM + BN (tensor-core) + bf16 K/V plane emission
    gemm_bn_kernel<<<dim3(NPIX / 128, HQKV / 64, NB), 256>>>(
        w_qkv, x, qkv_buf, HQKV, g_qkv, b_qkv, m_qkv, v_qkv, kv_bf);

    // 2) Attention -> att_buf
    attn_kernel<<<512, 256>>>(qkv_buf, kv_bf, att_buf);

    // 3) Depthwise conv + BN, add into att_buf
    pos_conv_kernel<<<(NB * DIMC * NPIX) / 256, 256>>>(
        qkv_buf, att_buf, w_pos, g_pos, b_pos, m_pos, v_pos);

    // 4) Proj GEMM + BN (tensor-core) -> d_out
    gemm_bn_kernel<<<dim3(NPIX / 128, DIMC / 64, NB), 256>>>(
        w_proj, att_buf, out, DIMC, g_proj, b_proj, m_proj, v_proj, nullptr);
}

// round 10
// speedup vs baseline: 2.5774x; 1.0052x over previous
#include <cuda_runtime.h>
#include <cuda_bf16.h>
#include <math.h>

#define DIMC 256
#define NHEADS 8
#define HEADD 32
#define KEYD 16
#define HQKV 512
#define NB 16
#define NPIX 1024
#define EPSV 1e-5f
// score scale folded with log2(e): softmax computed in exp2 domain
#define ATTN_SCALE_LOG2 (0.25f * 1.44269504088896f)

// Scratch (allocation-free rule: __device__ globals)
__device__ float g_qkv_buf[(size_t)NB * HQKV * NPIX];   // 33.5 MB: qkv[b][o][p]
__device__ float g_att_buf[(size_t)NB * DIMC * NPIX];   // 16.8 MB
// Per (b,h) plane (64*NPIX bf16):
//   [0:16384)      kT_hi [1024 pix][16 dims]
//   [16384:32768)  kT_lo [1024 pix][16 dims]
//   [32768:65536)  v_hi  [32 dims][1024 pix]
__device__ __nv_bfloat16 g_kv_bf[(size_t)NB * NHEADS * 64 * NPIX];

// ---------------------------------------------------------------------------
#define MMA16816(c, a, b0v, b1v)                                              \
    asm volatile(                                                             \
        "mma.sync.aligned.m16n8k16.row.col.f32.bf16.bf16.f32 "                \
        "{%0,%1,%2,%3}, {%4,%5,%6,%7}, {%8,%9}, {%0,%1,%2,%3};"               \
        : "+f"((c)[0]), "+f"((c)[1]), "+f"((c)[2]), "+f"((c)[3])              \
        : "r"((a)[0]), "r"((a)[1]), "r"((a)[2]), "r"((a)[3]),                 \
          "r"(b0v), "r"(b1v))

#define CP_ASYNC16(dst32, src)                                                \
    asm volatile("cp.async.cg.shared.global [%0], [%1], 16;"                  \
                 :: "r"(dst32), "l"(src))
#define CP_COMMIT asm volatile("cp.async.commit_group;")
#define CP_WAIT0  asm volatile("cp.async.wait_group 0;" ::: "memory")

// Split-pack: hi = bf16(v), lo = bf16(v - hi); element0 in low 16 bits.
__device__ __forceinline__ unsigned pack_hi2(float v0, float v1, unsigned& lo_out) {
    __nv_bfloat162 hh, ll;
    hh.x = __float2bfloat16_rn(v0);
    hh.y = __float2bfloat16_rn(v1);
    ll.x = __float2bfloat16_rn(v0 - __bfloat162float(hh.x));
    ll.y = __float2bfloat16_rn(v1 - __bfloat162float(hh.y));
    lo_out = *(unsigned*)&ll;
    return *(unsigned*)&hh;
}

__device__ __forceinline__ unsigned pack_bf16x2(float lo, float hi) {
    unsigned r;
    asm("cvt.rn.bf16x2.f32 %0, %1, %2;" : "=r"(r) : "f"(hi), "f"(lo));
    return r;
}

__device__ __forceinline__ float exp2a(float x) {
    float y;
    asm("ex2.approx.f32 %0, %1;" : "=f"(y) : "f"(x));
    return y;
}

// ---------------------------------------------------------------------------
// Tensor-core GEMM + BN, double-buffered smem, 2 CTAs/SM.
// If kvbuf != nullptr: emits kT hi/lo (transposed) and v hi bf16 planes.
// ---------------------------------------------------------------------------
__global__ void __launch_bounds__(256, 2)
gemm_bn_kernel(const float* __restrict__ W,
               const float* __restrict__ In,
               float* __restrict__ Out,
               int M,
               const float* __restrict__ gam,
               const float* __restrict__ bet,
               const float* __restrict__ mu,
               const float* __restrict__ var,
               __nv_bfloat16* __restrict__ kvbuf) {
    __shared__ __align__(16) __nv_bfloat16 Ws_h[2][64][24], Ws_l[2][64][24];
    __shared__ __align__(16) __nv_bfloat16 Bs_h[2][128][24], Bs_l[2][128][24];

    const int b = blockIdx.z;
    const int oBase = blockIdx.y * 64;
    const int pBase = blockIdx.x * 128;
    const int tid = threadIdx.x;
    const int warp = tid >> 5;
    const int lane = tid & 31;
    const int gr = lane >> 2;
    const int tc = lane & 3;
    const int o0 = (warp >> 1) * 16;
    const int p0 = (warp & 1) * 64;

    const float* inb = In + (size_t)b * DIMC * NPIX;

    const int sw_o = tid >> 2;
    const int sw_c = (tid & 3) * 4;
    const int sb_p = tid & 127;
    const int sb_cp = tid >> 7;

    float wreg[4];
    float inreg[8];

    // ---- prefetch + commit kstep 0 ----
    *(float4*)wreg = *(const float4*)&W[(size_t)(oBase + sw_o) * DIMC + sw_c];
#pragma unroll
    for (int j = 0; j < 4; j++) {
        int c = 2 * (sb_cp + 2 * j);
        inreg[2 * j]     = inb[(size_t)c * NPIX + pBase + sb_p];
        inreg[2 * j + 1] = inb[(size_t)(c + 1) * NPIX + pBase + sb_p];
    }
#pragma unroll
    for (int j = 0; j < 2; j++) {
        unsigned lo, hi = pack_hi2(wreg[2 * j], wreg[2 * j + 1], lo);
        *(unsigned*)&Ws_h[0][sw_o][sw_c + 2 * j] = hi;
        *(unsigned*)&Ws_l[0][sw_o][sw_c + 2 * j] = lo;
    }
#pragma unroll
    for (int j = 0; j < 4; j++) {
        int c = 2 * (sb_cp + 2 * j);
        unsigned lo, hi = pack_hi2(inreg[2 * j], inreg[2 * j + 1], lo);
        *(unsigned*)&Bs_h[0][sb_p][c] = hi;
        *(unsigned*)&Bs_l[0][sb_p][c] = lo;
    }
    __syncthreads();

    float C[8][4];
#pragma unroll
    for (int nt = 0; nt < 8; nt++)
#pragma unroll
        for (int r = 0; r < 4; r++) C[nt][r] = 0.f;

    for (int ks = 0; ks < 16; ks++) {
        const int cur = ks & 1;
        if (ks < 15) {
            int k0 = (ks + 1) * 16;
            *(float4*)wreg = *(const float4*)&W[(size_t)(oBase + sw_o) * DIMC + k0 + sw_c];
#pragma unroll
            for (int j = 0; j < 4; j++) {
                int c = k0 + 2 * (sb_cp + 2 * j);
                inreg[2 * j]     = inb[(size_t)c * NPIX + pBase + sb_p];
                inreg[2 * j + 1] = inb[(size_t)(c + 1) * NPIX + pBase + sb_p];
            }
        }

        unsigned ah[4], al[4];
        ah[0] = *(const unsigned*)&Ws_h[cur][o0 + gr][2 * tc];
        ah[1] = *(const unsigned*)&Ws_h[cur][o0 + gr + 8][2 * tc];
        ah[2] = *(const unsigned*)&Ws_h[cur][o0 + gr][2 * tc + 8];
        ah[3] = *(const unsigned*)&Ws_h[cur][o0 + gr + 8][2 * tc + 8];
        al[0] = *(const unsigned*)&Ws_l[cur][o0 + gr][2 * tc];
        al[1] = *(const unsigned*)&Ws_l[cur][o0 + gr + 8][2 * tc];
        al[2] = *(const unsigned*)&Ws_l[cur][o0 + gr][2 * tc + 8];
        al[3] = *(const unsigned*)&Ws_l[cur][o0 + gr + 8][2 * tc + 8];
#pragma unroll
        for (int nt = 0; nt < 8; nt++) {
            int p = p0 + nt * 8 + gr;
            unsigned bh0 = *(const unsigned*)&Bs_h[cur][p][2 * tc];
            unsigned bh1 = *(const unsigned*)&Bs_h[cur][p][2 * tc + 8];
            unsigned bl0 = *(const unsigned*)&Bs_l[cur][p][2 * tc];
            unsigned bl1 = *(const unsigned*)&Bs_l[cur][p][2 * tc + 8];
            MMA16816(C[nt], ah, bh0, bh1);
            MMA16816(C[nt], ah, bl0, bl1);
            MMA16816(C[nt], al, bh0, bh1);
        }

        if (ks < 15) {
            const int nxt = cur ^ 1;
#pragma unroll
            for (int j = 0; j < 2; j++) {
                unsigned lo, hi = pack_hi2(wreg[2 * j], wreg[2 * j + 1], lo);
                *(unsigned*)&Ws_h[nxt][sw_o][sw_c + 2 * j] = hi;
                *(unsigned*)&Ws_l[nxt][sw_o][sw_c + 2 * j] = lo;
            }
#pragma unroll
            for (int j = 0; j < 4; j++) {
                int c = 2 * (sb_cp + 2 * j);
                unsigned lo, hi = pack_hi2(inreg[2 * j], inreg[2 * j + 1], lo);
                *(unsigned*)&Bs_h[nxt][sb_p][c] = hi;
                *(unsigned*)&Bs_l[nxt][sb_p][c] = lo;
            }
            __syncthreads();
        }
    }

    // ---- epilogue: BN + store (+ optional kv plane emission) ----
    const int oG0 = oBase + o0 + gr;
    const int oG1 = oG0 + 8;
    float inv0 = rsqrtf(var[oG0] + EPSV) * gam[oG0];
    float add0 = bet[oG0] - mu[oG0] * inv0;
    float inv1 = rsqrtf(var[oG1] + EPSV) * gam[oG1];
    float add1 = bet[oG1] - mu[oG1] * inv1;

#pragma unroll
    for (int nt = 0; nt < 8; nt++) {
        int p = pBase + p0 + nt * 8 + 2 * tc;
        float2 r0, r1;
        r0.x = C[nt][0] * inv0 + add0;
        r0.y = C[nt][1] * inv0 + add0;
        r1.x = C[nt][2] * inv1 + add1;
        r1.y = C[nt][3] * inv1 + add1;
        *(float2*)&Out[((size_t)b * M + oG0) * NPIX + p] = r0;
        *(float2*)&Out[((size_t)b * M + oG1) * NPIX + p] = r1;

        if (kvbuf != nullptr) {
#pragma unroll
            for (int rr = 0; rr < 2; rr++) {
                int o = rr ? oG1 : oG0;
                float vx = rr ? r1.x : r0.x;
                float vy = rr ? r1.y : r0.y;
                int r64 = o & 63;
                if (r64 >= 16) {
                    int h = o >> 6;
                    __nv_bfloat16* hb = kvbuf + ((size_t)b * NHEADS + h) * (64 * NPIX);
                    if (r64 >= 32) {          // v: hi plane [32][1024]
                        unsigned hv = pack_bf16x2(vx, vy);
                        *(unsigned*)&hb[32768 + (size_t)(r64 - 32) * NPIX + p] = hv;
                    } else {                  // k: transposed hi/lo planes [1024][16]
                        int d = r64 - 16;
                        __nv_bfloat16 h0 = __float2bfloat16_rn(vx);
                        __nv_bfloat16 l0 = __float2bfloat16_rn(vx - __bfloat162float(h0));
                        __nv_bfloat16 h1 = __float2bfloat16_rn(vy);
                        __nv_bfloat16 l1 = __float2bfloat16_rn(vy - __bfloat162float(h1));
                        hb[(size_t)p * 16 + d] = h0;
                        hb[(size_t)(p + 1) * 16 + d] = h1;
                        hb[16384 + (size_t)p * 16 + d] = l0;
                        hb[16384 + (size_t)(p + 1) * 16 + d] = l1;
                    }
                }
            }
        }
    }
}

// ---------------------------------------------------------------------------
// FlashAttention-2, mma.sync bf16, cp.async KV staging, 2 CTAs/SM.
// Smem: two KV buffers; Qs (fp32, 16KB) aliases buffer 1 (only live in prologue).
// ---------------------------------------------------------------------------
struct KVBuf {
    __nv_bfloat16 Ks_h[64][24];   // 3072 B
    __nv_bfloat16 Ks_l[64][24];   // 3072 B
    __nv_bfloat16 Vt_h[32][72];   // 4608 B
};
#define KVBUF_BYTES 10752

__global__ void __launch_bounds__(256, 2)
attn_kernel(const float* __restrict__ qkv,
            const __nv_bfloat16* __restrict__ kvbf,
            float* __restrict__ att) {
    __shared__ __align__(16) char smem_raw[KVBUF_BYTES + 16 * 256 * 4];
    KVBuf* bufs[2];
    bufs[0] = (KVBuf*)smem_raw;
    bufs[1] = (KVBuf*)(smem_raw + KVBUF_BYTES);
    float (*Qs)[256] = (float(*)[256])(smem_raw + KVBUF_BYTES);   // alias buf 1

    const int blk = blockIdx.x;      // 0..511
    const int bh = blk >> 2;
    const int qq = blk & 3;
    const int b = bh >> 3;
    const int h = bh & 7;
    const float* base = qkv + ((size_t)b * HQKV + h * 64) * NPIX;
    const __nv_bfloat16* kvh = kvbf + ((size_t)b * NHEADS + h) * (64 * NPIX);
    float* ob = att + ((size_t)b * DIMC + h * HEADD) * NPIX;

    const int tid = threadIdx.x;
    const int warp = tid >> 5;
    const int lane = tid & 31;
    const int gr = lane >> 2;
    const int tc = lane & 3;
    const int qBase = qq * 256;

    // cp.async task mapping (per chunk: 2 x 16B per thread)
    const int kkey = (tid & 127) >> 1;        // key 0..63
    const int kho = (tid & 1) * 8;            // dim half 0/8
    const int vd = tid >> 3;                  // v dim 0..31
    const int vg = tid & 7;                   // key granule 0..7

    // ---- issue chunk 0 into buf0 (doesn't touch Qs alias) ----
    {
        const __nv_bfloat16* ksrc = kvh + ((tid < 128) ? 0 : 16384)
                                  + (size_t)kkey * 16 + kho;
        unsigned kdst = (unsigned)__cvta_generic_to_shared(
            (tid < 128) ? &bufs[0]->Ks_h[kkey][kho] : &bufs[0]->Ks_l[kkey][kho]);
        CP_ASYNC16(kdst, ksrc);
        unsigned vdst = (unsigned)__cvta_generic_to_shared(&bufs[0]->Vt_h[vd][vg * 8]);
        CP_ASYNC16(vdst, kvh + 32768 + (size_t)vd * NPIX + vg * 8);
        CP_COMMIT;
    }

    // ---- stage Q (scaled into exp2 domain) into aliased region ----
    for (int idx = tid; idx < 16 * 256; idx += 256) {
        int c = idx >> 8, p = idx & 255;
        Qs[c][p] = base[c * NPIX + qBase + p] * ATTN_SCALE_LOG2;
    }
    __syncthreads();

    // ---- Q fragments (bf16 hi only) ----
    unsigned qf[2][4];
#pragma unroll
    for (int qt = 0; qt < 2; qt++) {
        int q0 = warp * 32 + qt * 16 + gr;
#pragma unroll
        for (int r = 0; r < 4; r++) {
            int row = q0 + ((r & 1) ? 8 : 0);
            int k0 = 2 * tc + ((r & 2) ? 8 : 0);
            qf[qt][r] = pack_bf16x2(Qs[k0][row], Qs[k0 + 1][row]);
        }
    }
    CP_WAIT0;
    __syncthreads();   // chunk0 visible; all warps done reading Qs

    float m[2][2], l[2][2];
    float O[2][4][4];
#pragma unroll
    for (int qt = 0; qt < 2; qt++) {
        m[qt][0] = -1e30f; m[qt][1] = -1e30f;
        l[qt][0] = 0.f;    l[qt][1] = 0.f;
#pragma unroll
        for (int dt = 0; dt < 4; dt++)
#pragma unroll
            for (int r = 0; r < 4; r++) O[qt][dt][r] = 0.f;
    }

    for (int kb = 0; kb < 16; kb++) {
        const KVBuf* cb = bufs[kb & 1];
        const bool more = (kb < 15);
        // ---- issue next chunk into other buffer (async, overlaps MMA) ----
        if (more) {
            KVBuf* nb = bufs[(kb + 1) & 1];
            const size_t koff = (size_t)((kb + 1) * 64 + kkey) * 16 + kho;
            const __nv_bfloat16* ksrc = kvh + ((tid < 128) ? 0 : 16384) + koff;
            unsigned kdst = (unsigned)__cvta_generic_to_shared(
                (tid < 128) ? &nb->Ks_h[kkey][kho] : &nb->Ks_l[kkey][kho]);
            CP_ASYNC16(kdst, ksrc);
            unsigned vdst = (unsigned)__cvta_generic_to_shared(&nb->Vt_h[vd][vg * 8]);
            CP_ASYNC16(vdst, kvh + 32768 + (size_t)vd * NPIX + (kb + 1) * 64 + vg * 8);
            CP_COMMIT;
        }

        // ---- scores for both q-tiles ----
        float S[2][8][4];
#pragma unroll
        for (int nt = 0; nt < 8; nt++) {
            const int krow = nt * 8 + gr;
            unsigned bh0 = *(const unsigned*)&cb->Ks_h[krow][2 * tc];
            unsigned bh1 = *(const unsigned*)&cb->Ks_h[krow][2 * tc + 8];
            unsigned bl0 = *(const unsigned*)&cb->Ks_l[krow][2 * tc];
            unsigned bl1 = *(const unsigned*)&cb->Ks_l[krow][2 * tc + 8];
#pragma unroll
            for (int qt = 0; qt < 2; qt++) {
                S[qt][nt][0] = 0.f; S[qt][nt][1] = 0.f;
                S[qt][nt][2] = 0.f; S[qt][nt][3] = 0.f;
                MMA16816(S[qt][nt], qf[qt], bh0, bh1);
                MMA16816(S[qt][nt], qf[qt], bl0, bl1);
            }
        }

        // ---- online softmax (exp2 domain) ----
#pragma unroll
        for (int qt = 0; qt < 2; qt++) {
            float mx0 = -1e30f, mx1 = -1e30f;
#pragma unroll
            for (int nt = 0; nt < 8; nt++) {
                mx0 = fmaxf(mx0, fmaxf(S[qt][nt][0], S[qt][nt][1]));
                mx1 = fmaxf(mx1, fmaxf(S[qt][nt][2], S[qt][nt][3]));
            }
            mx0 = fmaxf(mx0, __shfl_xor_sync(0xffffffffu, mx0, 1));
            mx0 = fmaxf(mx0, __shfl_xor_sync(0xffffffffu, mx0, 2));
            mx1 = fmaxf(mx1, __shfl_xor_sync(0xffffffffu, mx1, 1));
            mx1 = fmaxf(mx1, __shfl_xor_sync(0xffffffffu, mx1, 2));

            float nm0 = fmaxf(m[qt][0], mx0);
            float nm1 = fmaxf(m[qt][1], mx1);
            float a0 = exp2a(m[qt][0] - nm0);
            float a1 = exp2a(m[qt][1] - nm1);
            m[qt][0] = nm0; m[qt][1] = nm1;

            float ls0 = 0.f, ls1 = 0.f;
#pragma unroll
            for (int nt = 0; nt < 8; nt++) {
                S[qt][nt][0] = exp2a(S[qt][nt][0] - nm0);
                S[qt][nt][1] = exp2a(S[qt][nt][1] - nm0);
                S[qt][nt][2] = exp2a(S[qt][nt][2] - nm1);
                S[qt][nt][3] = exp2a(S[qt][nt][3] - nm1);
                ls0 += S[qt][nt][0] + S[qt][nt][1];
                ls1 += S[qt][nt][2] + S[qt][nt][3];
            }
            ls0 += __shfl_xor_sync(0xffffffffu, ls0, 1);
            ls0 += __shfl_xor_sync(0xffffffffu, ls0, 2);
            ls1 += __shfl_xor_sync(0xffffffffu, ls1, 1);
            ls1 += __shfl_xor_sync(0xffffffffu, ls1, 2);
            l[qt][0] = l[qt][0] * a0 + ls0;
            l[qt][1] = l[qt][1] * a1 + ls1;

#pragma unroll
            for (int dt = 0; dt < 4; dt++) {
                O[qt][dt][0] *= a0; O[qt][dt][1] *= a0;
                O[qt][dt][2] *= a1; O[qt][dt][3] *= a1;
            }
        }

        // ---- AV: 1 MMA per (ks,dt,qt) ----
#pragma unroll
        for (int ks = 0; ks < 4; ks++) {
            unsigned ph[2][4];
#pragma unroll
            for (int qt = 0; qt < 2; qt++) {
                ph[qt][0] = pack_bf16x2(S[qt][2 * ks][0],     S[qt][2 * ks][1]);
                ph[qt][1] = pack_bf16x2(S[qt][2 * ks][2],     S[qt][2 * ks][3]);
                ph[qt][2] = pack_bf16x2(S[qt][2 * ks + 1][0], S[qt][2 * ks + 1][1]);
                ph[qt][3] = pack_bf16x2(S[qt][2 * ks + 1][2], S[qt][2 * ks + 1][3]);
            }
#pragma unroll
            for (int dt = 0; dt < 4; dt++) {
                const int dr = dt * 8 + gr;
                const int kc = ks * 16 + 2 * tc;
                unsigned vh0 = *(const unsigned*)&cb->Vt_h[dr][kc];
                unsigned vh1 = *(const unsigned*)&cb->Vt_h[dr][kc + 8];
                MMA16816(O[0][dt], ph[0], vh0, vh1);
                MMA16816(O[1][dt], ph[1], vh0, vh1);
            }
        }

        // ---- wait for next chunk copies, then flip ----
        if (more) {
            CP_WAIT0;
            __syncthreads();
        }
    }

    // ---- epilogue ----
#pragma unroll
    for (int qt = 0; qt < 2; qt++) {
        float r0 = 1.f / l[qt][0];
        float r1 = 1.f / l[qt][1];
        int q0 = qBase + warp * 32 + qt * 16 + gr;
        int q1 = q0 + 8;
#pragma unroll
        for (int dt = 0; dt < 4; dt++) {
            int d = dt * 8 + 2 * tc;
            ob[(size_t)d * NPIX + q0]       = O[qt][dt][0] * r0;
            ob[(size_t)(d + 1) * NPIX + q0] = O[qt][dt][1] * r0;
            ob[(size_t)d * NPIX + q1]       = O[qt][dt][2] * r1;
            ob[(size_t)(d + 1) * NPIX + q1] = O[qt][dt][3] * r1;
        }
    }
}

// ---------------------------------------------------------------------------
// Depthwise 3x3 conv on v_img + BN, added into attended buffer in-place.
// ---------------------------------------------------------------------------
__global__ void pos_conv_kernel(const float* __restrict__ qkv,
                                float* __restrict__ att,
                                const float* __restrict__ wpos,
                                const float* __restrict__ gam,
                                const float* __restrict__ bet,
                                const float* __restrict__ mu,
                                const float* __restrict__ var) {
    int idx = blockIdx.x * blockDim.x + threadIdx.x;
    if (idx >= NB * DIMC * NPIX) return;
    int p = idx & 1023;
    int ch = (idx >> 10) & 255;
    int b = idx >> 18;
    int y = p >> 5, x = p & 31;
    int o = ((ch >> 5) * 64) + 32 + (ch & 31);
    const float* vrow = qkv + ((size_t)b * HQKV + o) * NPIX;
    const float* wp = wpos + ch * 9;

    float acc = 0.f;
#pragma unroll
    for (int dy = 0; dy < 3; dy++) {
        int yy = y + dy - 1;
        if (yy < 0 || yy > 31) continue;
#pragma unroll
        for (int dx = 0; dx < 3; dx++) {
            int xx = x + dx - 1;
            if (xx < 0 || xx > 31) continue;
            acc += vrow[yy * 32 + xx] * wp[dy * 3 + dx];
        }
    }
    float inv = rsqrtf(var[ch] + EPSV) * gam[ch];
    att[idx] += acc * inv + (bet[ch] - mu[ch] * inv);
}

// ---------------------------------------------------------------------------
extern "C" void kernel_launch(void* const* d_in, const int* in_sizes, int n_in,
                              void* d_out, int out_size) {
    const float* x      = (const float*)d_in[0];
    const float* w_qkv  = (const float*)d_in[1];
    const float* g_qkv  = (const float*)d_in[2];
    const float* b_qkv  = (const float*)d_in[3];
    const float* m_qkv  = (const float*)d_in[4];
    const float* v_qkv  = (const float*)d_in[5];
    const float* w_pos  = (const float*)d_in[6];
    const float* g_pos  = (const float*)d_in[7];
    const float* b_pos  = (const float*)d_in[8];
    const float* m_pos  = (const float*)d_in[9];
    const float* v_pos  = (const float*)d_in[10];
    const float* w_proj = (const float*)d_in[11];
    const float* g_proj = (const float*)d_in[12];
    const float* b_proj = (const float*)d_in[13];
    const float* m_proj = (const float*)d_in[14];
    const float* v_proj = (const float*)d_in[15];
    float* out = (float*)d_out;

    float* qkv_buf = nullptr;
    float* att_buf = nullptr;
    __nv_bfloat16* kv_bf = nullptr;
    cudaGetSymbolAddress((void**)&qkv_buf, g_qkv_buf);
    cudaGetSymbolAddress((void**)&att_buf, g_att_buf);
    cudaGetSymbolAddress((void**)&kv_bf, g_kv_bf);

    // 1) QKV GEMM + BN (tensor-core) + kT/v bf16 plane emission
    gemm_bn_kernel<<<dim3(NPIX / 128, HQKV / 64, NB), 256>>>(
        w_qkv, x, qkv_buf, HQKV, g_qkv, b_qkv, m_qkv, v_qkv, kv_bf);

    // 2) Attention -> att_buf
    attn_kernel<<<512, 256>>>(qkv_buf, kv_bf, att_buf);

    // 3) Depthwise conv + BN, add into att_buf
    pos_conv_kernel<<<(NB * DIMC * NPIX) / 256, 256>>>(
        qkv_buf, att_buf, w_pos, g_pos, b_pos, m_pos, v_pos);

    // 4) Proj GEMM + BN (tensor-core) -> d_out
    gemm_bn_kernel<<<dim3(NPIX / 128, DIMC / 64, NB), 256>>>(
        w_proj, att_buf, out, DIMC, g_proj, b_proj, m_proj, v_proj, nullptr);
}

// round 11
// speedup vs baseline: 2.8976x; 1.1242x over previous
#include <cuda_runtime.h>
#include <cuda_bf16.h>
#include <math.h>

#define DIMC 256
#define NHEADS 8
#define HEADD 32
#define KEYD 16
#define HQKV 512
#define NB 16
#define NPIX 1024
#define EPSV 1e-5f
// score scale folded with log2(e): softmax computed in exp2 domain
#define ATTN_SCALE_LOG2 (0.25f * 1.44269504088896f)

// Scratch (allocation-free rule: __device__ globals)
__device__ float g_qkv_buf[(size_t)NB * HQKV * NPIX];   // 33.5 MB: qkv[b][o][p]
__device__ float g_att_buf[(size_t)NB * DIMC * NPIX];   // 16.8 MB
// Per (b,h) plane (64*NPIX bf16):
//   [0:16384)      kT_hi [1024 pix][16 dims]
//   [16384:32768)  kT_lo [1024 pix][16 dims]
//   [32768:65536)  v_hi  [32 dims][1024 pix]
__device__ __nv_bfloat16 g_kv_bf[(size_t)NB * NHEADS * 64 * NPIX];

// ---------------------------------------------------------------------------
#define MMA16816(c, a, b0v, b1v)                                              \
    asm volatile(                                                             \
        "mma.sync.aligned.m16n8k16.row.col.f32.bf16.bf16.f32 "                \
        "{%0,%1,%2,%3}, {%4,%5,%6,%7}, {%8,%9}, {%0,%1,%2,%3};"               \
        : "+f"((c)[0]), "+f"((c)[1]), "+f"((c)[2]), "+f"((c)[3])              \
        : "r"((a)[0]), "r"((a)[1]), "r"((a)[2]), "r"((a)[3]),                 \
          "r"(b0v), "r"(b1v))

#define CP_ASYNC16(dst32, src)                                                \
    asm volatile("cp.async.cg.shared.global [%0], [%1], 16;"                  \
                 :: "r"(dst32), "l"(src))
#define CP_COMMIT asm volatile("cp.async.commit_group;")
#define CP_WAIT0  asm volatile("cp.async.wait_group 0;" ::: "memory")

// Split-pack: hi = bf16(v), lo = bf16(v - hi); element0 in low 16 bits.
__device__ __forceinline__ unsigned pack_hi2(float v0, float v1, unsigned& lo_out) {
    __nv_bfloat162 hh, ll;
    hh.x = __float2bfloat16_rn(v0);
    hh.y = __float2bfloat16_rn(v1);
    ll.x = __float2bfloat16_rn(v0 - __bfloat162float(hh.x));
    ll.y = __float2bfloat16_rn(v1 - __bfloat162float(hh.y));
    lo_out = *(unsigned*)&ll;
    return *(unsigned*)&hh;
}

__device__ __forceinline__ unsigned pack_bf16x2(float lo, float hi) {
    unsigned r;
    asm("cvt.rn.bf16x2.f32 %0, %1, %2;" : "=r"(r) : "f"(hi), "f"(lo));
    return r;
}

__device__ __forceinline__ float exp2a(float x) {
    float y;
    asm("ex2.approx.f32 %0, %1;" : "=f"(y) : "f"(x));
    return y;
}

// ---------------------------------------------------------------------------
// Tensor-core GEMM + BN, double-buffered smem, 2 CTAs/SM.
// If kvbuf != nullptr: emits kT hi/lo (transposed) and v hi bf16 planes.
// ---------------------------------------------------------------------------
__global__ void __launch_bounds__(256, 2)
gemm_bn_kernel(const float* __restrict__ W,
               const float* __restrict__ In,
               float* __restrict__ Out,
               int M,
               const float* __restrict__ gam,
               const float* __restrict__ bet,
               const float* __restrict__ mu,
               const float* __restrict__ var,
               __nv_bfloat16* __restrict__ kvbuf) {
    __shared__ __align__(16) __nv_bfloat16 Ws_h[2][64][24], Ws_l[2][64][24];
    __shared__ __align__(16) __nv_bfloat16 Bs_h[2][128][24], Bs_l[2][128][24];

    const int b = blockIdx.z;
    const int oBase = blockIdx.y * 64;
    const int pBase = blockIdx.x * 128;
    const int tid = threadIdx.x;
    const int warp = tid >> 5;
    const int lane = tid & 31;
    const int gr = lane >> 2;
    const int tc = lane & 3;
    const int o0 = (warp >> 1) * 16;
    const int p0 = (warp & 1) * 64;

    const float* inb = In + (size_t)b * DIMC * NPIX;

    const int sw_o = tid >> 2;
    const int sw_c = (tid & 3) * 4;
    const int sb_p = tid & 127;
    const int sb_cp = tid >> 7;

    float wreg[4];
    float inreg[8];

    // ---- prefetch + commit kstep 0 ----
    *(float4*)wreg = *(const float4*)&W[(size_t)(oBase + sw_o) * DIMC + sw_c];
#pragma unroll
    for (int j = 0; j < 4; j++) {
        int c = 2 * (sb_cp + 2 * j);
        inreg[2 * j]     = inb[(size_t)c * NPIX + pBase + sb_p];
        inreg[2 * j + 1] = inb[(size_t)(c + 1) * NPIX + pBase + sb_p];
    }
#pragma unroll
    for (int j = 0; j < 2; j++) {
        unsigned lo, hi = pack_hi2(wreg[2 * j], wreg[2 * j + 1], lo);
        *(unsigned*)&Ws_h[0][sw_o][sw_c + 2 * j] = hi;
        *(unsigned*)&Ws_l[0][sw_o][sw_c + 2 * j] = lo;
    }
#pragma unroll
    for (int j = 0; j < 4; j++) {
        int c = 2 * (sb_cp + 2 * j);
        unsigned lo, hi = pack_hi2(inreg[2 * j], inreg[2 * j + 1], lo);
        *(unsigned*)&Bs_h[0][sb_p][c] = hi;
        *(unsigned*)&Bs_l[0][sb_p][c] = lo;
    }
    __syncthreads();

    float C[8][4];
#pragma unroll
    for (int nt = 0; nt < 8; nt++)
#pragma unroll
        for (int r = 0; r < 4; r++) C[nt][r] = 0.f;

    for (int ks = 0; ks < 16; ks++) {
        const int cur = ks & 1;
        if (ks < 15) {
            int k0 = (ks + 1) * 16;
            *(float4*)wreg = *(const float4*)&W[(size_t)(oBase + sw_o) * DIMC + k0 + sw_c];
#pragma unroll
            for (int j = 0; j < 4; j++) {
                int c = k0 + 2 * (sb_cp + 2 * j);
                inreg[2 * j]     = inb[(size_t)c * NPIX + pBase + sb_p];
                inreg[2 * j + 1] = inb[(size_t)(c + 1) * NPIX + pBase + sb_p];
            }
        }

        unsigned ah[4], al[4];
        ah[0] = *(const unsigned*)&Ws_h[cur][o0 + gr][2 * tc];
        ah[1] = *(const unsigned*)&Ws_h[cur][o0 + gr + 8][2 * tc];
        ah[2] = *(const unsigned*)&Ws_h[cur][o0 + gr][2 * tc + 8];
        ah[3] = *(const unsigned*)&Ws_h[cur][o0 + gr + 8][2 * tc + 8];
        al[0] = *(const unsigned*)&Ws_l[cur][o0 + gr][2 * tc];
        al[1] = *(const unsigned*)&Ws_l[cur][o0 + gr + 8][2 * tc];
        al[2] = *(const unsigned*)&Ws_l[cur][o0 + gr][2 * tc + 8];
        al[3] = *(const unsigned*)&Ws_l[cur][o0 + gr + 8][2 * tc + 8];
#pragma unroll
        for (int nt = 0; nt < 8; nt++) {
            int p = p0 + nt * 8 + gr;
            unsigned bh0 = *(const unsigned*)&Bs_h[cur][p][2 * tc];
            unsigned bh1 = *(const unsigned*)&Bs_h[cur][p][2 * tc + 8];
            unsigned bl0 = *(const unsigned*)&Bs_l[cur][p][2 * tc];
            unsigned bl1 = *(const unsigned*)&Bs_l[cur][p][2 * tc + 8];
            MMA16816(C[nt], ah, bh0, bh1);
            MMA16816(C[nt], ah, bl0, bl1);
            MMA16816(C[nt], al, bh0, bh1);
        }

        if (ks < 15) {
            const int nxt = cur ^ 1;
#pragma unroll
            for (int j = 0; j < 2; j++) {
                unsigned lo, hi = pack_hi2(wreg[2 * j], wreg[2 * j + 1], lo);
                *(unsigned*)&Ws_h[nxt][sw_o][sw_c + 2 * j] = hi;
                *(unsigned*)&Ws_l[nxt][sw_o][sw_c + 2 * j] = lo;
            }
#pragma unroll
            for (int j = 0; j < 4; j++) {
                int c = 2 * (sb_cp + 2 * j);
                unsigned lo, hi = pack_hi2(inreg[2 * j], inreg[2 * j + 1], lo);
                *(unsigned*)&Bs_h[nxt][sb_p][c] = hi;
                *(unsigned*)&Bs_l[nxt][sb_p][c] = lo;
            }
            __syncthreads();
        }
    }

    // ---- epilogue: BN + store (+ optional kv plane emission) ----
    const int oG0 = oBase + o0 + gr;
    const int oG1 = oG0 + 8;
    float inv0 = rsqrtf(var[oG0] + EPSV) * gam[oG0];
    float add0 = bet[oG0] - mu[oG0] * inv0;
    float inv1 = rsqrtf(var[oG1] + EPSV) * gam[oG1];
    float add1 = bet[oG1] - mu[oG1] * inv1;

#pragma unroll
    for (int nt = 0; nt < 8; nt++) {
        int p = pBase + p0 + nt * 8 + 2 * tc;
        float2 r0, r1;
        r0.x = C[nt][0] * inv0 + add0;
        r0.y = C[nt][1] * inv0 + add0;
        r1.x = C[nt][2] * inv1 + add1;
        r1.y = C[nt][3] * inv1 + add1;
        *(float2*)&Out[((size_t)b * M + oG0) * NPIX + p] = r0;
        *(float2*)&Out[((size_t)b * M + oG1) * NPIX + p] = r1;

        if (kvbuf != nullptr) {
#pragma unroll
            for (int rr = 0; rr < 2; rr++) {
                int o = rr ? oG1 : oG0;
                float vx = rr ? r1.x : r0.x;
                float vy = rr ? r1.y : r0.y;
                int r64 = o & 63;
                if (r64 >= 16) {
                    int h = o >> 6;
                    __nv_bfloat16* hb = kvbuf + ((size_t)b * NHEADS + h) * (64 * NPIX);
                    if (r64 >= 32) {          // v: hi plane [32][1024]
                        unsigned hv = pack_bf16x2(vx, vy);
                        *(unsigned*)&hb[32768 + (size_t)(r64 - 32) * NPIX + p] = hv;
                    } else {                  // k: transposed hi/lo planes [1024][16]
                        int d = r64 - 16;
                        __nv_bfloat16 h0 = __float2bfloat16_rn(vx);
                        __nv_bfloat16 l0 = __float2bfloat16_rn(vx - __bfloat162float(h0));
                        __nv_bfloat16 h1 = __float2bfloat16_rn(vy);
                        __nv_bfloat16 l1 = __float2bfloat16_rn(vy - __bfloat162float(h1));
                        hb[(size_t)p * 16 + d] = h0;
                        hb[(size_t)(p + 1) * 16 + d] = h1;
                        hb[16384 + (size_t)p * 16 + d] = l0;
                        hb[16384 + (size_t)(p + 1) * 16 + d] = l1;
                    }
                }
            }
        }
    }
}

// ---------------------------------------------------------------------------
// FlashAttention without online softmax: scores are bounded (BN'd inputs,
// |s|<~30 in exp2 domain << fp32 range), so P = exp2(s) raw, l accumulated
// as per-thread partials, ONE shfl-reduce in the epilogue. No max tracking,
// no O rescale, no per-chunk shfl chains.
// ---------------------------------------------------------------------------
struct KVBuf {
    __nv_bfloat16 Ks_h[64][24];   // 3072 B
    __nv_bfloat16 Ks_l[64][24];   // 3072 B
    __nv_bfloat16 Vt_h[32][72];   // 4608 B
};
#define KVBUF_BYTES 10752

__global__ void __launch_bounds__(256, 2)
attn_kernel(const float* __restrict__ qkv,
            const __nv_bfloat16* __restrict__ kvbf,
            float* __restrict__ att) {
    __shared__ __align__(16) char smem_raw[KVBUF_BYTES + 16 * 256 * 4];
    KVBuf* bufs[2];
    bufs[0] = (KVBuf*)smem_raw;
    bufs[1] = (KVBuf*)(smem_raw + KVBUF_BYTES);
    float (*Qs)[256] = (float(*)[256])(smem_raw + KVBUF_BYTES);   // alias buf 1

    const int blk = blockIdx.x;      // 0..511
    const int bh = blk >> 2;
    const int qq = blk & 3;
    const int b = bh >> 3;
    const int h = bh & 7;
    const float* base = qkv + ((size_t)b * HQKV + h * 64) * NPIX;
    const __nv_bfloat16* kvh = kvbf + ((size_t)b * NHEADS + h) * (64 * NPIX);
    float* ob = att + ((size_t)b * DIMC + h * HEADD) * NPIX;

    const int tid = threadIdx.x;
    const int warp = tid >> 5;
    const int lane = tid & 31;
    const int gr = lane >> 2;
    const int tc = lane & 3;
    const int qBase = qq * 256;

    // cp.async task mapping (per chunk: 2 x 16B per thread)
    const int kkey = (tid & 127) >> 1;        // key 0..63
    const int kho = (tid & 1) * 8;            // dim half 0/8
    const int vd = tid >> 3;                  // v dim 0..31
    const int vg = tid & 7;                   // key granule 0..7

    // ---- issue chunk 0 into buf0 (doesn't touch Qs alias) ----
    {
        const __nv_bfloat16* ksrc = kvh + ((tid < 128) ? 0 : 16384)
                                  + (size_t)kkey * 16 + kho;
        unsigned kdst = (unsigned)__cvta_generic_to_shared(
            (tid < 128) ? &bufs[0]->Ks_h[kkey][kho] : &bufs[0]->Ks_l[kkey][kho]);
        CP_ASYNC16(kdst, ksrc);
        unsigned vdst = (unsigned)__cvta_generic_to_shared(&bufs[0]->Vt_h[vd][vg * 8]);
        CP_ASYNC16(vdst, kvh + 32768 + (size_t)vd * NPIX + vg * 8);
        CP_COMMIT;
    }

    // ---- stage Q (scaled into exp2 domain) into aliased region ----
    for (int idx = tid; idx < 16 * 256; idx += 256) {
        int c = idx >> 8, p = idx & 255;
        Qs[c][p] = base[c * NPIX + qBase + p] * ATTN_SCALE_LOG2;
    }
    __syncthreads();

    // ---- Q fragments (bf16 hi only) ----
    unsigned qf[2][4];
#pragma unroll
    for (int qt = 0; qt < 2; qt++) {
        int q0 = warp * 32 + qt * 16 + gr;
#pragma unroll
        for (int r = 0; r < 4; r++) {
            int row = q0 + ((r & 1) ? 8 : 0);
            int k0 = 2 * tc + ((r & 2) ? 8 : 0);
            qf[qt][r] = pack_bf16x2(Qs[k0][row], Qs[k0 + 1][row]);
        }
    }
    CP_WAIT0;
    __syncthreads();   // chunk0 visible; all warps done reading Qs

    float lp[2][2];     // per-thread partial sum of P, [qtile][row half]
    float O[2][4][4];
#pragma unroll
    for (int qt = 0; qt < 2; qt++) {
        lp[qt][0] = 0.f; lp[qt][1] = 0.f;
#pragma unroll
        for (int dt = 0; dt < 4; dt++)
#pragma unroll
            for (int r = 0; r < 4; r++) O[qt][dt][r] = 0.f;
    }

    for (int kb = 0; kb < 16; kb++) {
        const KVBuf* cb = bufs[kb & 1];
        const bool more = (kb < 15);
        // ---- issue next chunk into other buffer (async, overlaps MMA) ----
        if (more) {
            KVBuf* nb = bufs[(kb + 1) & 1];
            const size_t koff = (size_t)((kb + 1) * 64 + kkey) * 16 + kho;
            const __nv_bfloat16* ksrc = kvh + ((tid < 128) ? 0 : 16384) + koff;
            unsigned kdst = (unsigned)__cvta_generic_to_shared(
                (tid < 128) ? &nb->Ks_h[kkey][kho] : &nb->Ks_l[kkey][kho]);
            CP_ASYNC16(kdst, ksrc);
            unsigned vdst = (unsigned)__cvta_generic_to_shared(&nb->Vt_h[vd][vg * 8]);
            CP_ASYNC16(vdst, kvh + 32768 + (size_t)vd * NPIX + (kb + 1) * 64 + vg * 8);
            CP_COMMIT;
        }

        // ---- scores for both q-tiles ----
        float S[2][8][4];
#pragma unroll
        for (int nt = 0; nt < 8; nt++) {
            const int krow = nt * 8 + gr;
            unsigned bh0 = *(const unsigned*)&cb->Ks_h[krow][2 * tc];
            unsigned bh1 = *(const unsigned*)&cb->Ks_h[krow][2 * tc + 8];
            unsigned bl0 = *(const unsigned*)&cb->Ks_l[krow][2 * tc];
            unsigned bl1 = *(const unsigned*)&cb->Ks_l[krow][2 * tc + 8];
#pragma unroll
            for (int qt = 0; qt < 2; qt++) {
                S[qt][nt][0] = 0.f; S[qt][nt][1] = 0.f;
                S[qt][nt][2] = 0.f; S[qt][nt][3] = 0.f;
                MMA16816(S[qt][nt], qf[qt], bh0, bh1);
                MMA16816(S[qt][nt], qf[qt], bl0, bl1);
            }
        }

        // ---- P = exp2(S) raw; accumulate partial l ----
#pragma unroll
        for (int qt = 0; qt < 2; qt++) {
#pragma unroll
            for (int nt = 0; nt < 8; nt++) {
                S[qt][nt][0] = exp2a(S[qt][nt][0]);
                S[qt][nt][1] = exp2a(S[qt][nt][1]);
                S[qt][nt][2] = exp2a(S[qt][nt][2]);
                S[qt][nt][3] = exp2a(S[qt][nt][3]);
                lp[qt][0] += S[qt][nt][0] + S[qt][nt][1];
                lp[qt][1] += S[qt][nt][2] + S[qt][nt][3];
            }
        }

        // ---- AV: 1 MMA per (ks,dt,qt) ----
#pragma unroll
        for (int ks = 0; ks < 4; ks++) {
            unsigned ph[2][4];
#pragma unroll
            for (int qt = 0; qt < 2; qt++) {
                ph[qt][0] = pack_bf16x2(S[qt][2 * ks][0],     S[qt][2 * ks][1]);
                ph[qt][1] = pack_bf16x2(S[qt][2 * ks][2],     S[qt][2 * ks][3]);
                ph[qt][2] = pack_bf16x2(S[qt][2 * ks + 1][0], S[qt][2 * ks + 1][1]);
                ph[qt][3] = pack_bf16x2(S[qt][2 * ks + 1][2], S[qt][2 * ks + 1][3]);
            }
#pragma unroll
            for (int dt = 0; dt < 4; dt++) {
                const int dr = dt * 8 + gr;
                const int kc = ks * 16 + 2 * tc;
                unsigned vh0 = *(const unsigned*)&cb->Vt_h[dr][kc];
                unsigned vh1 = *(const unsigned*)&cb->Vt_h[dr][kc + 8];
                MMA16816(O[0][dt], ph[0], vh0, vh1);
                MMA16816(O[1][dt], ph[1], vh0, vh1);
            }
        }

        // ---- wait for next chunk copies, then flip ----
        if (more) {
            CP_WAIT0;
            __syncthreads();
        }
    }

    // ---- epilogue: one shfl-reduce of l per row, normalize, store ----
#pragma unroll
    for (int qt = 0; qt < 2; qt++) {
        float l0 = lp[qt][0], l1 = lp[qt][1];
        l0 += __shfl_xor_sync(0xffffffffu, l0, 1);
        l0 += __shfl_xor_sync(0xffffffffu, l0, 2);
        l1 += __shfl_xor_sync(0xffffffffu, l1, 1);
        l1 += __shfl_xor_sync(0xffffffffu, l1, 2);
        float r0 = 1.f / l0;
        float r1 = 1.f / l1;
        int q0 = qBase + warp * 32 + qt * 16 + gr;
        int q1 = q0 + 8;
#pragma unroll
        for (int dt = 0; dt < 4; dt++) {
            int d = dt * 8 + 2 * tc;
            ob[(size_t)d * NPIX + q0]       = O[qt][dt][0] * r0;
            ob[(size_t)(d + 1) * NPIX + q0] = O[qt][dt][1] * r0;
            ob[(size_t)d * NPIX + q1]       = O[qt][dt][2] * r1;
            ob[(size_t)(d + 1) * NPIX + q1] = O[qt][dt][3] * r1;
        }
    }
}

// ---------------------------------------------------------------------------
// Depthwise 3x3 conv on v_img + BN, added into attended buffer in-place.
// ---------------------------------------------------------------------------
__global__ void pos_conv_kernel(const float* __restrict__ qkv,
                                float* __restrict__ att,
                                const float* __restrict__ wpos,
                                const float* __restrict__ gam,
                                const float* __restrict__ bet,
                                const float* __restrict__ mu,
                                const float* __restrict__ var) {
    int idx = blockIdx.x * blockDim.x + threadIdx.x;
    if (idx >= NB * DIMC * NPIX) return;
    int p = idx & 1023;
    int ch = (idx >> 10) & 255;
    int b = idx >> 18;
    int y = p >> 5, x = p & 31;
    int o = ((ch >> 5) * 64) + 32 + (ch & 31);
    const float* vrow = qkv + ((size_t)b * HQKV + o) * NPIX;
    const float* wp = wpos + ch * 9;

    float acc = 0.f;
#pragma unroll
    for (int dy = 0; dy < 3; dy++) {
        int yy = y + dy - 1;
        if (yy < 0 || yy > 31) continue;
#pragma unroll
        for (int dx = 0; dx < 3; dx++) {
            int xx = x + dx - 1;
            if (xx < 0 || xx > 31) continue;
            acc += vrow[yy * 32 + xx] * wp[dy * 3 + dx];
        }
    }
    float inv = rsqrtf(var[ch] + EPSV) * gam[ch];
    att[idx] += acc * inv + (bet[ch] - mu[ch] * inv);
}

// ---------------------------------------------------------------------------
extern "C" void kernel_launch(void* const* d_in, const int* in_sizes, int n_in,
                              void* d_out, int out_size) {
    const float* x      = (const float*)d_in[0];
    const float* w_qkv  = (const float*)d_in[1];
    const float* g_qkv  = (const float*)d_in[2];
    const float* b_qkv  = (const float*)d_in[3];
    const float* m_qkv  = (const float*)d_in[4];
    const float* v_qkv  = (const float*)d_in[5];
    const float* w_pos  = (const float*)d_in[6];
    const float* g_pos  = (const float*)d_in[7];
    const float* b_pos  = (const float*)d_in[8];
    const float* m_pos  = (const float*)d_in[9];
    const float* v_pos  = (const float*)d_in[10];
    const float* w_proj = (const float*)d_in[11];
    const float* g_proj = (const float*)d_in[12];
    const float* b_proj = (const float*)d_in[13];
    const float* m_proj = (const float*)d_in[14];
    const float* v_proj = (const float*)d_in[15];
    float* out = (float*)d_out;

    float* qkv_buf = nullptr;
    float* att_buf = nullptr;
    __nv_bfloat16* kv_bf = nullptr;
    cudaGetSymbolAddress((void**)&qkv_buf, g_qkv_buf);
    cudaGetSymbolAddress((void**)&att_buf, g_att_buf);
    cudaGetSymbolAddress((void**)&kv_bf, g_kv_bf);

    // 1) QKV GEMM + BN (tensor-core) + kT/v bf16 plane emission
    gemm_bn_kernel<<<dim3(NPIX / 128, HQKV / 64, NB), 256>>>(
        w_qkv, x, qkv_buf, HQKV, g_qkv, b_qkv, m_qkv, v_qkv, kv_bf);

    // 2) Attention -> att_buf
    attn_kernel<<<512, 256>>>(qkv_buf, kv_bf, att_buf);

    // 3) Depthwise conv + BN, add into att_buf
    pos_conv_kernel<<<(NB * DIMC * NPIX) / 256, 256>>>(
        qkv_buf, att_buf, w_pos, g_pos, b_pos, m_pos, v_pos);

    // 4) Proj GEMM + BN (tensor-core) -> d_out
    gemm_bn_kernel<<<dim3(NPIX / 128, DIMC / 64, NB), 256>>>(
        w_proj, att_buf, out, DIMC, g_proj, b_proj, m_proj, v_proj, nullptr);
}

// round 14
// speedup vs baseline: 2.9476x; 1.0173x over previous
#include <cuda_runtime.h>
#include <cuda_bf16.h>
#include <math.h>

#define DIMC 256
#define NHEADS 8
#define HEADD 32
#define KEYD 16
#define HQKV 512
#define NB 16
#define NPIX 1024
#define EPSV 1e-5f
// score scale folded with log2(e): softmax computed in exp2 domain
#define ATTN_SCALE_LOG2 (0.25f * 1.44269504088896f)

// Scratch (allocation-free rule: __device__ globals)
__device__ float g_qkv_buf[(size_t)NB * HQKV * NPIX];   // 33.5 MB: qkv[b][o][p]
__device__ float g_att_buf[(size_t)NB * DIMC * NPIX];   // 16.8 MB
// Per (b,h) plane (64*NPIX bf16):
//   [0:16384)      kT_hi [1024 pix][16 dims]
//   [16384:32768)  kT_lo [1024 pix][16 dims]
//   [32768:65536)  v_hi  [32 dims][1024 pix]
__device__ __nv_bfloat16 g_kv_bf[(size_t)NB * NHEADS * 64 * NPIX];

// ---------------------------------------------------------------------------
#define MMA16816(c, a, b0v, b1v)                                              \
    asm volatile(                                                             \
        "mma.sync.aligned.m16n8k16.row.col.f32.bf16.bf16.f32 "                \
        "{%0,%1,%2,%3}, {%4,%5,%6,%7}, {%8,%9}, {%0,%1,%2,%3};"               \
        : "+f"((c)[0]), "+f"((c)[1]), "+f"((c)[2]), "+f"((c)[3])              \
        : "r"((a)[0]), "r"((a)[1]), "r"((a)[2]), "r"((a)[3]),                 \
          "r"(b0v), "r"(b1v))

#define CP_ASYNC16(dst32, src)                                                \
    asm volatile("cp.async.cg.shared.global [%0], [%1], 16;"                  \
                 :: "r"(dst32), "l"(src))
#define CP_COMMIT asm volatile("cp.async.commit_group;")
#define CP_WAIT0  asm volatile("cp.async.wait_group 0;" ::: "memory")

// Split-pack: hi = bf16(v), lo = bf16(v - hi); element0 in low 16 bits.
__device__ __forceinline__ unsigned pack_hi2(float v0, float v1, unsigned& lo_out) {
    __nv_bfloat162 hh, ll;
    hh.x = __float2bfloat16_rn(v0);
    hh.y = __float2bfloat16_rn(v1);
    ll.x = __float2bfloat16_rn(v0 - __bfloat162float(hh.x));
    ll.y = __float2bfloat16_rn(v1 - __bfloat162float(hh.y));
    lo_out = *(unsigned*)&ll;
    return *(unsigned*)&hh;
}

__device__ __forceinline__ unsigned pack_bf16x2(float lo, float hi) {
    unsigned r;
    asm("cvt.rn.bf16x2.f32 %0, %1, %2;" : "=r"(r) : "f"(hi), "f"(lo));
    return r;
}

__device__ __forceinline__ float exp2a(float x) {
    float y;
    asm("ex2.approx.f32 %0, %1;" : "=f"(y) : "f"(x));
    return y;
}

// ---------------------------------------------------------------------------
// Tensor-core GEMM + BN, double-buffered smem, 2 CTAs/SM.
// W hi/lo + In hi/lo, 3-MMA split (fp32-grade; W truncation is correlated
// error — proven 2e-3 failure when dropped, so W_lo stays).
// If kvbuf != nullptr: emits kT hi/lo (transposed) and v hi bf16 planes.
// ---------------------------------------------------------------------------
__global__ void __launch_bounds__(256, 2)
gemm_bn_kernel(const float* __restrict__ W,
               const float* __restrict__ In,
               float* __restrict__ Out,
               int M,
               const float* __restrict__ gam,
               const float* __restrict__ bet,
               const float* __restrict__ mu,
               const float* __restrict__ var,
               __nv_bfloat16* __restrict__ kvbuf) {
    __shared__ __align__(16) __nv_bfloat16 Ws_h[2][64][24], Ws_l[2][64][24];
    __shared__ __align__(16) __nv_bfloat16 Bs_h[2][128][24], Bs_l[2][128][24];

    const int b = blockIdx.z;
    const int oBase = blockIdx.y * 64;
    const int pBase = blockIdx.x * 128;
    const int tid = threadIdx.x;
    const int warp = tid >> 5;
    const int lane = tid & 31;
    const int gr = lane >> 2;
    const int tc = lane & 3;
    const int o0 = (warp >> 1) * 16;
    const int p0 = (warp & 1) * 64;

    const float* inb = In + (size_t)b * DIMC * NPIX;

    const int sw_o = tid >> 2;
    const int sw_c = (tid & 3) * 4;
    const int sb_p = tid & 127;
    const int sb_cp = tid >> 7;

    float wreg[4];
    float inreg[8];

    // ---- prefetch + commit kstep 0 ----
    *(float4*)wreg = *(const float4*)&W[(size_t)(oBase + sw_o) * DIMC + sw_c];
#pragma unroll
    for (int j = 0; j < 4; j++) {
        int c = 2 * (sb_cp + 2 * j);
        inreg[2 * j]     = inb[(size_t)c * NPIX + pBase + sb_p];
        inreg[2 * j + 1] = inb[(size_t)(c + 1) * NPIX + pBase + sb_p];
    }
#pragma unroll
    for (int j = 0; j < 2; j++) {
        unsigned lo, hi = pack_hi2(wreg[2 * j], wreg[2 * j + 1], lo);
        *(unsigned*)&Ws_h[0][sw_o][sw_c + 2 * j] = hi;
        *(unsigned*)&Ws_l[0][sw_o][sw_c + 2 * j] = lo;
    }
#pragma unroll
    for (int j = 0; j < 4; j++) {
        int c = 2 * (sb_cp + 2 * j);
        unsigned lo, hi = pack_hi2(inreg[2 * j], inreg[2 * j + 1], lo);
        *(unsigned*)&Bs_h[0][sb_p][c] = hi;
        *(unsigned*)&Bs_l[0][sb_p][c] = lo;
    }
    __syncthreads();

    float C[8][4];
#pragma unroll
    for (int nt = 0; nt < 8; nt++)
#pragma unroll
        for (int r = 0; r < 4; r++) C[nt][r] = 0.f;

    for (int ks = 0; ks < 16; ks++) {
        const int cur = ks & 1;
        if (ks < 15) {
            int k0 = (ks + 1) * 16;
            *(float4*)wreg = *(const float4*)&W[(size_t)(oBase + sw_o) * DIMC + k0 + sw_c];
#pragma unroll
            for (int j = 0; j < 4; j++) {
                int c = k0 + 2 * (sb_cp + 2 * j);
                inreg[2 * j]     = inb[(size_t)c * NPIX + pBase + sb_p];
                inreg[2 * j + 1] = inb[(size_t)(c + 1) * NPIX + pBase + sb_p];
            }
        }

        unsigned ah[4], al[4];
        ah[0] = *(const unsigned*)&Ws_h[cur][o0 + gr][2 * tc];
        ah[1] = *(const unsigned*)&Ws_h[cur][o0 + gr + 8][2 * tc];
        ah[2] = *(const unsigned*)&Ws_h[cur][o0 + gr][2 * tc + 8];
        ah[3] = *(const unsigned*)&Ws_h[cur][o0 + gr + 8][2 * tc + 8];
        al[0] = *(const unsigned*)&Ws_l[cur][o0 + gr][2 * tc];
        al[1] = *(const unsigned*)&Ws_l[cur][o0 + gr + 8][2 * tc];
        al[2] = *(const unsigned*)&Ws_l[cur][o0 + gr][2 * tc + 8];
        al[3] = *(const unsigned*)&Ws_l[cur][o0 + gr + 8][2 * tc + 8];
#pragma unroll
        for (int nt = 0; nt < 8; nt++) {
            int p = p0 + nt * 8 + gr;
            unsigned bh0 = *(const unsigned*)&Bs_h[cur][p][2 * tc];
            unsigned bh1 = *(const unsigned*)&Bs_h[cur][p][2 * tc + 8];
            unsigned bl0 = *(const unsigned*)&Bs_l[cur][p][2 * tc];
            unsigned bl1 = *(const unsigned*)&Bs_l[cur][p][2 * tc + 8];
            MMA16816(C[nt], ah, bh0, bh1);
            MMA16816(C[nt], ah, bl0, bl1);
            MMA16816(C[nt], al, bh0, bh1);
        }

        if (ks < 15) {
            const int nxt = cur ^ 1;
#pragma unroll
            for (int j = 0; j < 2; j++) {
                unsigned lo, hi = pack_hi2(wreg[2 * j], wreg[2 * j + 1], lo);
                *(unsigned*)&Ws_h[nxt][sw_o][sw_c + 2 * j] = hi;
                *(unsigned*)&Ws_l[nxt][sw_o][sw_c + 2 * j] = lo;
            }
#pragma unroll
            for (int j = 0; j < 4; j++) {
                int c = 2 * (sb_cp + 2 * j);
                unsigned lo, hi = pack_hi2(inreg[2 * j], inreg[2 * j + 1], lo);
                *(unsigned*)&Bs_h[nxt][sb_p][c] = hi;
                *(unsigned*)&Bs_l[nxt][sb_p][c] = lo;
            }
            __syncthreads();
        }
    }

    // ---- epilogue: BN + store (+ optional kv plane emission) ----
    const int oG0 = oBase + o0 + gr;
    const int oG1 = oG0 + 8;
    float inv0 = rsqrtf(var[oG0] + EPSV) * gam[oG0];
    float add0 = bet[oG0] - mu[oG0] * inv0;
    float inv1 = rsqrtf(var[oG1] + EPSV) * gam[oG1];
    float add1 = bet[oG1] - mu[oG1] * inv1;

#pragma unroll
    for (int nt = 0; nt < 8; nt++) {
        int p = pBase + p0 + nt * 8 + 2 * tc;
        float2 r0, r1;
        r0.x = C[nt][0] * inv0 + add0;
        r0.y = C[nt][1] * inv0 + add0;
        r1.x = C[nt][2] * inv1 + add1;
        r1.y = C[nt][3] * inv1 + add1;
        *(float2*)&Out[((size_t)b * M + oG0) * NPIX + p] = r0;
        *(float2*)&Out[((size_t)b * M + oG1) * NPIX + p] = r1;

        if (kvbuf != nullptr) {
#pragma unroll
            for (int rr = 0; rr < 2; rr++) {
                int o = rr ? oG1 : oG0;
                float vx = rr ? r1.x : r0.x;
                float vy = rr ? r1.y : r0.y;
                int r64 = o & 63;
                if (r64 >= 16) {
                    int h = o >> 6;
                    __nv_bfloat16* hb = kvbuf + ((size_t)b * NHEADS + h) * (64 * NPIX);
                    if (r64 >= 32) {          // v: hi plane [32][1024]
                        unsigned hv = pack_bf16x2(vx, vy);
                        *(unsigned*)&hb[32768 + (size_t)(r64 - 32) * NPIX + p] = hv;
                    } else {                  // k: transposed hi/lo planes [1024][16]
                        int d = r64 - 16;
                        __nv_bfloat16 h0 = __float2bfloat16_rn(vx);
                        __nv_bfloat16 l0 = __float2bfloat16_rn(vx - __bfloat162float(h0));
                        __nv_bfloat16 h1 = __float2bfloat16_rn(vy);
                        __nv_bfloat16 l1 = __float2bfloat16_rn(vy - __bfloat162float(h1));
                        hb[(size_t)p * 16 + d] = h0;
                        hb[(size_t)(p + 1) * 16 + d] = h1;
                        hb[16384 + (size_t)p * 16 + d] = l0;
                        hb[16384 + (size_t)(p + 1) * 16 + d] = l1;
                    }
                }
            }
        }
    }
}

// ---------------------------------------------------------------------------
// Attention without online softmax (bounded scores). Chunk body structured
// as 4 independent per-ks blocks (QK MMA -> exp2 -> pack -> AV MMA) so
// tensor and MUFU pipes interleave instead of alternating in bursts.
// ---------------------------------------------------------------------------
struct KVBuf {
    __nv_bfloat16 Ks_h[64][24];   // 3072 B
    __nv_bfloat16 Ks_l[64][24];   // 3072 B
    __nv_bfloat16 Vt_h[32][72];   // 4608 B
};
#define KVBUF_BYTES 10752

__global__ void __launch_bounds__(256, 2)
attn_kernel(const float* __restrict__ qkv,
            const __nv_bfloat16* __restrict__ kvbf,
            float* __restrict__ att) {
    __shared__ __align__(16) char smem_raw[KVBUF_BYTES + 16 * 256 * 4];
    KVBuf* bufs[2];
    bufs[0] = (KVBuf*)smem_raw;
    bufs[1] = (KVBuf*)(smem_raw + KVBUF_BYTES);
    float (*Qs)[256] = (float(*)[256])(smem_raw + KVBUF_BYTES);   // alias buf 1

    const int blk = blockIdx.x;      // 0..511
    const int bh = blk >> 2;
    const int qq = blk & 3;
    const int b = bh >> 3;
    const int h = bh & 7;
    const float* base = qkv + ((size_t)b * HQKV + h * 64) * NPIX;
    const __nv_bfloat16* kvh = kvbf + ((size_t)b * NHEADS + h) * (64 * NPIX);
    float* ob = att + ((size_t)b * DIMC + h * HEADD) * NPIX;

    const int tid = threadIdx.x;
    const int warp = tid >> 5;
    const int lane = tid & 31;
    const int gr = lane >> 2;
    const int tc = lane & 3;
    const int qBase = qq * 256;

    // cp.async task mapping (per chunk: 2 x 16B per thread)
    const int kkey = (tid & 127) >> 1;        // key 0..63
    const int kho = (tid & 1) * 8;            // dim half 0/8
    const int vd = tid >> 3;                  // v dim 0..31
    const int vg = tid & 7;                   // key granule 0..7

    // ---- issue chunk 0 into buf0 (doesn't touch Qs alias) ----
    {
        const __nv_bfloat16* ksrc = kvh + ((tid < 128) ? 0 : 16384)
                                  + (size_t)kkey * 16 + kho;
        unsigned kdst = (unsigned)__cvta_generic_to_shared(
            (tid < 128) ? &bufs[0]->Ks_h[kkey][kho] : &bufs[0]->Ks_l[kkey][kho]);
        CP_ASYNC16(kdst, ksrc);
        unsigned vdst = (unsigned)__cvta_generic_to_shared(&bufs[0]->Vt_h[vd][vg * 8]);
        CP_ASYNC16(vdst, kvh + 32768 + (size_t)vd * NPIX + vg * 8);
        CP_COMMIT;
    }

    // ---- stage Q (scaled into exp2 domain) into aliased region ----
    for (int idx = tid; idx < 16 * 256; idx += 256) {
        int c = idx >> 8, p = idx & 255;
        Qs[c][p] = base[c * NPIX + qBase + p] * ATTN_SCALE_LOG2;
    }
    __syncthreads();

    // ---- Q fragments (bf16 hi only) ----
    unsigned qf[2][4];
#pragma unroll
    for (int qt = 0; qt < 2; qt++) {
        int q0 = warp * 32 + qt * 16 + gr;
#pragma unroll
        for (int r = 0; r < 4; r++) {
            int row = q0 + ((r & 1) ? 8 : 0);
            int k0 = 2 * tc + ((r & 2) ? 8 : 0);
            qf[qt][r] = pack_bf16x2(Qs[k0][row], Qs[k0 + 1][row]);
        }
    }
    CP_WAIT0;
    __syncthreads();   // chunk0 visible; all warps done reading Qs

    float lp[2][2];     // per-thread partial sum of P, [qtile][row half]
    float O[2][4][4];
#pragma unroll
    for (int qt = 0; qt < 2; qt++) {
        lp[qt][0] = 0.f; lp[qt][1] = 0.f;
#pragma unroll
        for (int dt = 0; dt < 4; dt++)
#pragma unroll
            for (int r = 0; r < 4; r++) O[qt][dt][r] = 0.f;
    }

    for (int kb = 0; kb < 16; kb++) {
        const KVBuf* cb = bufs[kb & 1];
        const bool more = (kb < 15);
        // ---- issue next chunk into other buffer (async, overlaps MMA) ----
        if (more) {
            KVBuf* nb = bufs[(kb + 1) & 1];
            const size_t koff = (size_t)((kb + 1) * 64 + kkey) * 16 + kho;
            const __nv_bfloat16* ksrc = kvh + ((tid < 128) ? 0 : 16384) + koff;
            unsigned kdst = (unsigned)__cvta_generic_to_shared(
                (tid < 128) ? &nb->Ks_h[kkey][kho] : &nb->Ks_l[kkey][kho]);
            CP_ASYNC16(kdst, ksrc);
            unsigned vdst = (unsigned)__cvta_generic_to_shared(&nb->Vt_h[vd][vg * 8]);
            CP_ASYNC16(vdst, kvh + 32768 + (size_t)vd * NPIX + (kb + 1) * 64 + vg * 8);
            CP_COMMIT;
        }

        // ---- 4 independent 16-key blocks: QK -> exp2 -> pack -> AV ----
#pragma unroll
        for (int ks = 0; ks < 4; ks++) {
            float S[2][2][4];   // [qt][j][reg], j = ntile within this ks
#pragma unroll
            for (int j = 0; j < 2; j++) {
                const int krow = (2 * ks + j) * 8 + gr;
                unsigned bh0 = *(const unsigned*)&cb->Ks_h[krow][2 * tc];
                unsigned bh1 = *(const unsigned*)&cb->Ks_h[krow][2 * tc + 8];
                unsigned bl0 = *(const unsigned*)&cb->Ks_l[krow][2 * tc];
                unsigned bl1 = *(const unsigned*)&cb->Ks_l[krow][2 * tc + 8];
#pragma unroll
                for (int qt = 0; qt < 2; qt++) {
                    S[qt][j][0] = 0.f; S[qt][j][1] = 0.f;
                    S[qt][j][2] = 0.f; S[qt][j][3] = 0.f;
                    MMA16816(S[qt][j], qf[qt], bh0, bh1);
                    MMA16816(S[qt][j], qf[qt], bl0, bl1);
                }
            }

            unsigned ph[2][4];
#pragma unroll
            for (int qt = 0; qt < 2; qt++) {
#pragma unroll
                for (int j = 0; j < 2; j++) {
                    S[qt][j][0] = exp2a(S[qt][j][0]);
                    S[qt][j][1] = exp2a(S[qt][j][1]);
                    S[qt][j][2] = exp2a(S[qt][j][2]);
                    S[qt][j][3] = exp2a(S[qt][j][3]);
                    lp[qt][0] += S[qt][j][0] + S[qt][j][1];
                    lp[qt][1] += S[qt][j][2] + S[qt][j][3];
                }
                ph[qt][0] = pack_bf16x2(S[qt][0][0], S[qt][0][1]);
                ph[qt][1] = pack_bf16x2(S[qt][0][2], S[qt][0][3]);
                ph[qt][2] = pack_bf16x2(S[qt][1][0], S[qt][1][1]);
                ph[qt][3] = pack_bf16x2(S[qt][1][2], S[qt][1][3]);
            }

#pragma unroll
            for (int dt = 0; dt < 4; dt++) {
                const int dr = dt * 8 + gr;
                const int kc = ks * 16 + 2 * tc;
                unsigned vh0 = *(const unsigned*)&cb->Vt_h[dr][kc];
                unsigned vh1 = *(const unsigned*)&cb->Vt_h[dr][kc + 8];
                MMA16816(O[0][dt], ph[0], vh0, vh1);
                MMA16816(O[1][dt], ph[1], vh0, vh1);
            }
        }

        // ---- wait for next chunk copies, then flip ----
        if (more) {
            CP_WAIT0;
            __syncthreads();
        }
    }

    // ---- epilogue: one shfl-reduce of l per row, normalize, store ----
#pragma unroll
    for (int qt = 0; qt < 2; qt++) {
        float l0 = lp[qt][0], l1 = lp[qt][1];
        l0 += __shfl_xor_sync(0xffffffffu, l0, 1);
        l0 += __shfl_xor_sync(0xffffffffu, l0, 2);
        l1 += __shfl_xor_sync(0xffffffffu, l1, 1);
        l1 += __shfl_xor_sync(0xffffffffu, l1, 2);
        float r0 = 1.f / l0;
        float r1 = 1.f / l1;
        int q0 = qBase + warp * 32 + qt * 16 + gr;
        int q1 = q0 + 8;
#pragma unroll
        for (int dt = 0; dt < 4; dt++) {
            int d = dt * 8 + 2 * tc;
            ob[(size_t)d * NPIX + q0]       = O[qt][dt][0] * r0;
            ob[(size_t)(d + 1) * NPIX + q0] = O[qt][dt][1] * r0;
            ob[(size_t)d * NPIX + q1]       = O[qt][dt][2] * r1;
            ob[(size_t)(d + 1) * NPIX + q1] = O[qt][dt][3] * r1;
        }
    }
}

// ---------------------------------------------------------------------------
// Depthwise 3x3 conv on v_img + BN, added into attended buffer in-place.
// ---------------------------------------------------------------------------
__global__ void pos_conv_kernel(const float* __restrict__ qkv,
                                float* __restrict__ att,
                                const float* __restrict__ wpos,
                                const float* __restrict__ gam,
                                const float* __restrict__ bet,
                                const float* __restrict__ mu,
                                const float* __restrict__ var) {
    int idx = blockIdx.x * blockDim.x + threadIdx.x;
    if (idx >= NB * DIMC * NPIX) return;
    int p = idx & 1023;
    int ch = (idx >> 10) & 255;
    int b = idx >> 18;
    int y = p >> 5, x = p & 31;
    int o = ((ch >> 5) * 64) + 32 + (ch & 31);
    const float* vrow = qkv + ((size_t)b * HQKV + o) * NPIX;
    const float* wp = wpos + ch * 9;

    float acc = 0.f;
#pragma unroll
    for (int dy = 0; dy < 3; dy++) {
        int yy = y + dy - 1;
        if (yy < 0 || yy > 31) continue;
#pragma unroll
        for (int dx = 0; dx < 3; dx++) {
            int xx = x + dx - 1;
            if (xx < 0 || xx > 31) continue;
            acc += vrow[yy * 32 + xx] * wp[dy * 3 + dx];
        }
    }
    float inv = rsqrtf(var[ch] + EPSV) * gam[ch];
    att[idx] += acc * inv + (bet[ch] - mu[ch] * inv);
}

// ---------------------------------------------------------------------------
extern "C" void kernel_launch(void* const* d_in, const int* in_sizes, int n_in,
                              void* d_out, int out_size) {
    const float* x      = (const float*)d_in[0];
    const float* w_qkv  = (const float*)d_in[1];
    const float* g_qkv  = (const float*)d_in[2];
    const float* b_qkv  = (const float*)d_in[3];
    const float* m_qkv  = (const float*)d_in[4];
    const float* v_qkv  = (const float*)d_in[5];
    const float* w_pos  = (const float*)d_in[6];
    const float* g_pos  = (const float*)d_in[7];
    const float* b_pos  = (const float*)d_in[8];
    const float* m_pos  = (const float*)d_in[9];
    const float* v_pos  = (const float*)d_in[10];
    const float* w_proj = (const float*)d_in[11];
    const float* g_proj = (const float*)d_in[12];
    const float* b_proj = (const float*)d_in[13];
    const float* m_proj = (const float*)d_in[14];
    const float* v_proj = (const float*)d_in[15];
    float* out = (float*)d_out;

    float* qkv_buf = nullptr;
    float* att_buf = nullptr;
    __nv_bfloat16* kv_bf = nullptr;
    cudaGetSymbolAddress((void**)&qkv_buf, g_qkv_buf);
    cudaGetSymbolAddress((void**)&att_buf, g_att_buf);
    cudaGetSymbolAddress((void**)&kv_bf, g_kv_bf);

    // 1) QKV GEMM + BN (tensor-core) + kT/v bf16 plane emission
    gemm_bn_kernel<<<dim3(NPIX / 128, HQKV / 64, NB), 256>>>(
        w_qkv, x, qkv_buf, HQKV, g_qkv, b_qkv, m_qkv, v_qkv, kv_bf);

    // 2) Attention -> att_buf
    attn_kernel<<<512, 256>>>(qkv_buf, kv_bf, att_buf);

    // 3) Depthwise conv + BN, add into att_buf
    pos_conv_kernel<<<(NB * DIMC * NPIX) / 256, 256>>>(
        qkv_buf, att_buf, w_pos, g_pos, b_pos, m_pos, v_pos);

    // 4) Proj GEMM + BN (tensor-core) -> d_out
    gemm_bn_kernel<<<dim3(NPIX / 128, DIMC / 64, NB), 256>>>(
        w_proj, att_buf, out, DIMC, g_proj, b_proj, m_proj, v_proj, nullptr);
}